// round 11
// baseline (speedup 1.0000x reference)
#include <cuda_runtime.h>
#include <cuda_bf16.h>
#include <cstdint>

// Problem dims
#define EDIM 512
#define BB   16
#define SS   1024
#define HH   8
#define DD   64
#define MTOT (BB*SS)   // 16384
#define LL   4

typedef __nv_bfloat16 bf16;

// ---------------- scratch (device globals; no allocation allowed) ----------
__device__ bf16 g_qh[(size_t)MTOT*EDIM];
__device__ bf16 g_kh[(size_t)MTOT*EDIM];
__device__ bf16 g_vh[(size_t)MTOT*EDIM], g_vl[(size_t)MTOT*EDIM];
__device__ bf16 g_Wqh[EDIM*EDIM];
__device__ bf16 g_Wkh[EDIM*EDIM];
__device__ bf16 g_Wvh[EDIM*EDIM], g_Wvl[EDIM*EDIM];
__device__ bf16 g_Woh[EDIM*EDIM], g_Wol[EDIM*EDIM];
__device__ float g_bv[EDIM], g_bo[EDIM];
__device__ bf16 g_Qh[(size_t)MTOT*EDIM];           // projected Q (hi only)
__device__ bf16 g_Kh[(size_t)MTOT*EDIM];           // projected K (hi only)
__device__ bf16 g_Vh[(size_t)MTOT*EDIM], g_Vl[(size_t)MTOT*EDIM];
__device__ bf16 g_Ch[(size_t)MTOT*EDIM], g_Cl[(size_t)MTOT*EDIM];
__device__ float g_vsum[BB*EDIM];                  // masked column sums of input v
__device__ float g_Mv[BB*EDIM];
__device__ float g_Msum[BB];

// ======================= helpers ===========================================
__device__ __forceinline__ uint32_t smem_u32(const void* p) {
    uint32_t a;
    asm("{ .reg .u64 t; cvta.to.shared.u64 t, %1; cvt.u32.u64 %0, t; }"
        : "=r"(a) : "l"(p));
    return a;
}

__device__ __forceinline__ void ldsm_x4(uint32_t addr, uint32_t r[4]) {
    asm volatile("ldmatrix.sync.aligned.m8n8.x4.shared.b16 {%0,%1,%2,%3}, [%4];"
        : "=r"(r[0]), "=r"(r[1]), "=r"(r[2]), "=r"(r[3]) : "r"(addr));
}

__device__ __forceinline__ void ldsm_x4_t(uint32_t addr, uint32_t r[4]) {
    asm volatile("ldmatrix.sync.aligned.m8n8.x4.trans.shared.b16 {%0,%1,%2,%3}, [%4];"
        : "=r"(r[0]), "=r"(r[1]), "=r"(r[2]), "=r"(r[3]) : "r"(addr));
}

__device__ __forceinline__ void mma_bf16(float d[4], const uint32_t a[4],
                                         const uint32_t b[2]) {
    asm volatile(
        "mma.sync.aligned.m16n8k16.row.col.f32.bf16.bf16.f32 "
        "{%0,%1,%2,%3}, {%4,%5,%6,%7}, {%8,%9}, {%0,%1,%2,%3};"
        : "+f"(d[0]), "+f"(d[1]), "+f"(d[2]), "+f"(d[3])
        : "r"(a[0]), "r"(a[1]), "r"(a[2]), "r"(a[3]), "r"(b[0]), "r"(b[1]));
}

__device__ __forceinline__ uint32_t pack_bf16x2(float lo, float hi) {
    uint32_t r;
    asm("cvt.rn.bf16x2.f32 %0, %1, %2;" : "=r"(r) : "f"(hi), "f"(lo));
    return r;
}

__device__ __forceinline__ void split1(float x, bf16& h, bf16& l) {
    h = __float2bfloat16_rn(x);
    l = __float2bfloat16_rn(x - __bfloat162float(h));
}

__device__ __forceinline__ void split_pack4(const float4 v, uint2& hi, uint2& lo) {
    bf16 hx, hy, hz, hw, lx, ly, lz, lw;
    split1(v.x, hx, lx); split1(v.y, hy, ly);
    split1(v.z, hz, lz); split1(v.w, hw, lw);
    __nv_bfloat162 h01 = __nv_bfloat162(hx, hy), h23 = __nv_bfloat162(hz, hw);
    __nv_bfloat162 l01 = __nv_bfloat162(lx, ly), l23 = __nv_bfloat162(lz, lw);
    hi.x = *(uint32_t*)&h01; hi.y = *(uint32_t*)&h23;
    lo.x = *(uint32_t*)&l01; lo.y = *(uint32_t*)&l23;
}

// expm1(x) for |x| <~ 0.5
__device__ __forceinline__ float expm1_poly(float x) {
    float c = 8.33333333e-3f;
    c = fmaf(c, x, 4.16666667e-2f);
    c = fmaf(c, x, 1.66666667e-1f);
    c = fmaf(c, x, 0.5f);
    c = fmaf(c, x, 1.0f);
    return x * c;
}

__device__ __forceinline__ int resolve_lang(const int* langp) {
    int lang = langp[0];
    if (lang < 0 || lang >= LL) {
        float f = __int_as_float(lang);
        int li = (int)f;
        lang = (li >= 0 && li < LL) ? li : 0;
    }
    return lang;
}

__device__ __forceinline__ void cp16(uint32_t dst, const void* src) {
    asm volatile("cp.async.cg.shared.global [%0], [%1], 16;"
                 :: "r"(dst), "l"(src) : "memory");
}
__device__ __forceinline__ void cp_commit() {
    asm volatile("cp.async.commit_group;" ::: "memory");
}
__device__ __forceinline__ void cp_wait0() {
    asm volatile("cp.async.wait_group 0;" ::: "memory");
}
__device__ __forceinline__ void cp_wait1() {
    asm volatile("cp.async.wait_group 1;" ::: "memory");
}

// ---------------- consolidated prep ----------------------------------------
// blocks [0,8192): q->hi | [8192,16384): k->hi | [16384,24576): v->hi/lo
// [24576,25600): weight fuse/split | [25600,25632): masked v column sums
// [25632,25648): mask counts
#define PREP_BLKS 25648

__global__ __launch_bounds__(256) void prep_kernel(
    const float* __restrict__ q, const float* __restrict__ k,
    const float* __restrict__ v,
    const float* __restrict__ Wq, const float* __restrict__ Wk,
    const float* __restrict__ Wvs, const float* __restrict__ Wvp,
    const float* __restrict__ bvs, const float* __restrict__ bvp,
    const float* __restrict__ Wos, const float* __restrict__ Wop,
    const float* __restrict__ bos, const float* __restrict__ bop,
    const int*  __restrict__ mask, const int* __restrict__ langp)
{
    const int blk = blockIdx.x, tid = threadIdx.x;
    if (blk < 24576) {
        int which = blk >> 13;
        size_t i = ((size_t)(blk & 8191))*256 + tid;
        const float* src = (which == 0) ? q : (which == 1) ? k : v;
        float4 val = *(const float4*)(src + i*4);
        uint2 h, l;
        split_pack4(val, h, l);
        if (which == 0)      *(uint2*)(g_qh + i*4) = h;
        else if (which == 1) *(uint2*)(g_kh + i*4) = h;
        else { *(uint2*)(g_vh + i*4) = h; *(uint2*)(g_vl + i*4) = l; }
    } else if (blk < 25600) {
        int i = (blk - 24576)*256 + tid;
        int lang = resolve_lang(langp);
        size_t off = (size_t)lang * EDIM * EDIM + i;
        g_Wqh[i] = __float2bfloat16_rn(Wq[i]);
        g_Wkh[i] = __float2bfloat16_rn(Wk[i]);
        split1(Wvs[i] * Wvp[off], g_Wvh[i], g_Wvl[i]);
        split1(Wos[i] * Wop[off], g_Woh[i], g_Wol[i]);
        if (i < EDIM) {
            g_bv[i] = bvs[i] + bvp[lang*EDIM + i];
            g_bo[i] = bos[i] + bop[lang*EDIM + i];
        }
    } else if (blk < 25632) {
        int j = blk - 25600;
        int b = j >> 1, e = (j & 1)*256 + tid;
        float acc = 0.f;
#pragma unroll 4
        for (int s = 0; s < SS; s++)
            if (mask[b*SS + s] != 0)
                acc += v[(size_t)(b*SS + s)*EDIM + e];
        g_vsum[b*EDIM + e] = acc;
    } else {
        int b = blk - 25632;
        __shared__ int cnt[256];
        int c = 0;
        for (int s = tid; s < SS; s += 256) c += (mask[b*SS + s] != 0);
        cnt[tid] = c;
        __syncthreads();
#pragma unroll
        for (int off = 128; off; off >>= 1) {
            if (tid < off) cnt[tid] += cnt[tid + off];
            __syncthreads();
        }
        if (tid == 0) g_Msum[b] = (float)cnt[0];
    }
}

// ---------------- Mv = vsum @ Wv^T + cnt*bv (tiny fp32 GEMM) ---------------
__global__ __launch_bounds__(128) void mv_gemm()
{
    __shared__ float vs[EDIM];
    const int b = blockIdx.y;
    const int d = blockIdx.x*128 + threadIdx.x;
    for (int i = threadIdx.x; i < EDIM; i += 128) vs[i] = g_vsum[b*EDIM + i];
    __syncthreads();
    float acc = 0.f;
#pragma unroll 8
    for (int e = 0; e < EDIM; e++) {
        float w = __bfloat162float(g_Wvh[(size_t)d*EDIM + e])
                + __bfloat162float(g_Wvl[(size_t)d*EDIM + e]);
        acc = fmaf(vs[e], w, acc);
    }
    g_Mv[b*EDIM + d] = acc + g_Msum[b]*g_bv[d];
}

// =================== cp.async bf16 GEMM core ===============================
#define GS_ROW   40
#define GS_ARRB  10240                     // bytes per array per stage (128*40*2)

template<int MODE, int NPROD>
__device__ __forceinline__ void gemm_core(
    const bf16* __restrict__ Ahi, const bf16* __restrict__ Alo,
    const bf16* __restrict__ Bhi, const bf16* __restrict__ Blo,
    const float* __restrict__ bias, float scale,
    float* __restrict__ outF, bf16* __restrict__ outHi, bf16* __restrict__ outLo)
{
    extern __shared__ __align__(128) bf16 smem[];
    constexpr int NARR = (NPROD == 3) ? 4 : 2;
    constexpr uint32_t STAGEB = NARR * GS_ARRB;

    const int tid  = threadIdx.x;
    const int lane = tid & 31;
    const int wid  = tid >> 5;
    const int wm   = wid >> 1;
    const int wn   = wid & 1;
    const int m0   = blockIdx.y * 128;
    const int n0   = blockIdx.x * 128;

    const uint32_t sb = smem_u32(smem);

    auto cp_stage = [&](int ks, int buf) {
        uint32_t sbase = sb + (uint32_t)buf * STAGEB;
#pragma unroll
        for (int c8 = 0; c8 < NARR*2; c8++) {
            int j = c8*256 + tid;
            int arr = j >> 9, jj = j & 511;
            int row = jj >> 2, cc = jj & 3;
            const bf16* src;
            if (NPROD == 3) {
                if      (arr == 0) src = Ahi + (size_t)(m0+row)*EDIM + ks*32 + cc*8;
                else if (arr == 1) src = Alo + (size_t)(m0+row)*EDIM + ks*32 + cc*8;
                else if (arr == 2) src = Bhi + (size_t)(n0+row)*EDIM + ks*32 + cc*8;
                else               src = Blo + (size_t)(n0+row)*EDIM + ks*32 + cc*8;
            } else {
                src = (arr == 0) ? Ahi + (size_t)(m0+row)*EDIM + ks*32 + cc*8
                                 : Bhi + (size_t)(n0+row)*EDIM + ks*32 + cc*8;
            }
            uint32_t dst = sbase + (uint32_t)arr*GS_ARRB + (uint32_t)(row*GS_ROW + cc*8)*2;
            cp16(dst, src);
        }
        cp_commit();
    };

    float d[2][8][4];
#pragma unroll
    for (int mt = 0; mt < 2; mt++)
#pragma unroll
        for (int nt = 0; nt < 8; nt++)
#pragma unroll
            for (int u = 0; u < 4; u++) d[mt][nt][u] = 0.f;

    cp_stage(0, 0);
    cp_stage(1, 1);

    for (int ks = 0; ks < 16; ks++) {
        if (ks < 15) cp_wait1(); else cp_wait0();
        __syncthreads();
        if (ks + 2 < 16) cp_stage(ks + 2, (ks + 2) % 3);

        const uint32_t base = sb + (uint32_t)(ks % 3) * STAGEB;
        const uint32_t aHi = base;
        const uint32_t aLo = base + GS_ARRB;
        const uint32_t bHi = base + (NPROD == 3 ? 2 : 1)*GS_ARRB;
        const uint32_t bLo = base + 3*GS_ARRB;

#pragma unroll
        for (int kk = 0; kk < 2; kk++) {
            const int kc = kk * 16;
            uint32_t ah[2][4], al[2][4];
            {
                int r = wm*32 + (lane & 7) + ((lane >> 3) & 1)*8;
                int k = kc + ((lane >> 4) & 1)*8;
                uint32_t off = (uint32_t)(r*GS_ROW + k)*2;
#pragma unroll
                for (int mt = 0; mt < 2; mt++) {
                    ldsm_x4(aHi + off + (uint32_t)(mt*16*GS_ROW)*2, ah[mt]);
                    if (NPROD == 3)
                        ldsm_x4(aLo + off + (uint32_t)(mt*16*GS_ROW)*2, al[mt]);
                }
            }
            uint32_t bh[8][2], bl[8][2];
            {
                int n = wn*64 + (lane & 7) + ((lane >> 4) & 1)*8;
                int k = kc + ((lane >> 3) & 1)*8;
                uint32_t off = (uint32_t)(n*GS_ROW + k)*2;
#pragma unroll
                for (int q = 0; q < 4; q++) {
                    uint32_t r4[4];
                    ldsm_x4(bHi + off + (uint32_t)(q*16*GS_ROW)*2, r4);
                    bh[2*q][0] = r4[0]; bh[2*q][1] = r4[1];
                    bh[2*q+1][0] = r4[2]; bh[2*q+1][1] = r4[3];
                    if (NPROD == 3) {
                        ldsm_x4(bLo + off + (uint32_t)(q*16*GS_ROW)*2, r4);
                        bl[2*q][0] = r4[0]; bl[2*q][1] = r4[1];
                        bl[2*q+1][0] = r4[2]; bl[2*q+1][1] = r4[3];
                    }
                }
            }
#pragma unroll
            for (int mt = 0; mt < 2; mt++)
#pragma unroll
                for (int nt = 0; nt < 8; nt++) {
                    mma_bf16(d[mt][nt], ah[mt], bh[nt]);
                    if (NPROD == 3) {
                        mma_bf16(d[mt][nt], ah[mt], bl[nt]);
                        mma_bf16(d[mt][nt], al[mt], bh[nt]);
                    }
                }
        }
    }

    // ---------------- epilogue --------------------------------------------
#pragma unroll
    for (int mt = 0; mt < 2; mt++) {
        int row0 = m0 + wm*32 + mt*16 + (lane >> 2);
#pragma unroll
        for (int nt = 0; nt < 8; nt++) {
            int col = n0 + wn*64 + nt*8 + (lane & 3)*2;
            float b0 = bias[col], b1 = bias[col + 1];
            float v0 = (d[mt][nt][0] + b0) * scale;
            float v1 = (d[mt][nt][1] + b1) * scale;
            float v2 = (d[mt][nt][2] + b0) * scale;
            float v3 = (d[mt][nt][3] + b1) * scale;
            size_t o0 = (size_t)row0*EDIM + col;
            size_t o1 = (size_t)(row0 + 8)*EDIM + col;
            if (MODE == 0) {
                *(float2*)(outF + o0) = make_float2(v0, v1);
                *(float2*)(outF + o1) = make_float2(v2, v3);
            } else {
                uint32_t h0 = pack_bf16x2(v0, v1), h1 = pack_bf16x2(v2, v3);
                *(uint32_t*)(outHi + o0) = h0;
                *(uint32_t*)(outHi + o1) = h1;
                if (MODE == 2) {
                    float f0 = __uint_as_float(h0 << 16);
                    float f1 = __uint_as_float(h0 & 0xffff0000u);
                    float f2 = __uint_as_float(h1 << 16);
                    float f3 = __uint_as_float(h1 & 0xffff0000u);
                    *(uint32_t*)(outLo + o0) = pack_bf16x2(v0 - f0, v1 - f1);
                    *(uint32_t*)(outLo + o1) = pack_bf16x2(v2 - f2, v3 - f3);
                }
            }
        }
    }
}

template<int MODE, int NPROD>
__global__ __launch_bounds__(256, 1) void gemm_mma(
    const bf16* __restrict__ Ahi, const bf16* __restrict__ Alo,
    const bf16* __restrict__ Bhi, const bf16* __restrict__ Blo,
    const float* __restrict__ bias, float scale,
    float* __restrict__ outF, bf16* __restrict__ outHi, bf16* __restrict__ outLo)
{
    gemm_core<MODE, NPROD>(Ahi, Alo, Bhi, Blo, bias, scale, outF, outHi, outLo);
}

// batched Q+K projections (blockIdx.z selects the problem)
__global__ __launch_bounds__(256, 1) void gemm_qk(
    const bf16* __restrict__ Aq, const bf16* __restrict__ Ak,
    const bf16* __restrict__ Wqh, const bf16* __restrict__ Wkh,
    const float* __restrict__ bq, const float* __restrict__ bk,
    bf16* __restrict__ oq, bf16* __restrict__ ok)
{
    if (blockIdx.z == 0)
        gemm_core<1,1>(Aq, nullptr, Wqh, nullptr, bq, 1.0f/64.0f, nullptr, oq, nullptr);
    else
        gemm_core<1,1>(Ak, nullptr, Wkh, nullptr, bk, 1.0f, nullptr, ok, nullptr);
}

// =================== attention: single-bf16 QK, trans-ldmatrix PV ==========
#define AT_ROW   72
#define AT_QOFF  0
#define AT_KV(buf)   (18432 + (buf)*36864)
#define AT_VOFF(buf) (AT_KV(buf) + 18432)
#define AT_MASK  92160
#define ATTN_SMEM (92160 + 1024)

__global__ __launch_bounds__(256, 1) void attn_mma(
    const bf16* __restrict__ Qh, const bf16* __restrict__ Kh,
    const bf16* __restrict__ Vh, const int* __restrict__ mask,
    const float* __restrict__ Mv, const float* __restrict__ Msum,
    bf16* __restrict__ Ch, bf16* __restrict__ Cl)
{
    extern __shared__ __align__(128) bf16 sm[];

    const int tid  = threadIdx.x;
    const int lane = tid & 31;
    const int wid  = tid >> 5;
    const int b    = blockIdx.z, h = blockIdx.y;
    const int q0   = blockIdx.x * 128;

    const uint32_t sb = smem_u32(sm);
    float* maskf = (float*)((char*)sm + AT_MASK);   // [2][128]

    auto cp_kv = [&](int kb, int buf) {
#pragma unroll
        for (int c8 = 0; c8 < 8; c8++) {
            int j = c8*256 + tid;
            int arr = j >> 10, jj = j & 1023;
            int row = jj >> 3, cc = jj & 7;
            const bf16* src = (arr ? Vh : Kh)
                + (size_t)(b*SS + kb*128 + row)*EDIM + h*DD + cc*8;
            uint32_t dst = sb + (arr ? AT_VOFF(buf) : AT_KV(buf))
                + (uint32_t)(row*AT_ROW + cc*8)*2;
            cp16(dst, src);
        }
        cp_commit();
    };

    // ---- Q tile (plain loads) + mask buf0 ----
#pragma unroll
    for (int c4 = 0; c4 < 4; c4++) {
        int j = c4*256 + tid;
        int row = j >> 3, cc = j & 7;
        uint4 v = *(const uint4*)(Qh + (size_t)(b*SS + q0 + row)*EDIM + h*DD + cc*8);
        uint32_t dst = sb + AT_QOFF + (uint32_t)(row*AT_ROW + cc*8)*2;
        asm volatile("st.shared.v4.b32 [%0], {%1,%2,%3,%4};"
                     :: "r"(dst), "r"(v.x), "r"(v.y), "r"(v.z), "r"(v.w));
    }
    if (tid < 128) maskf[tid] = (mask[b*SS + tid] != 0) ? 1.f : 0.f;
    cp_kv(0, 0);
    __syncthreads();

    // ---- Q fragments (single bf16) ----
    uint32_t qf[4][4];
    {
        int r = wid*16 + (lane & 7) + ((lane >> 3) & 1)*8;
#pragma unroll
        for (int kc = 0; kc < 4; kc++) {
            int k = kc*16 + ((lane >> 4) & 1)*8;
            ldsm_x4(sb + AT_QOFF + (uint32_t)(r*AT_ROW + k)*2, qf[kc]);
        }
    }

    float l0 = 0.f, l1 = 0.f;
    float O[8][4];
#pragma unroll
    for (int nt = 0; nt < 8; nt++)
#pragma unroll
        for (int u = 0; u < 4; u++) O[nt][u] = 0.f;

    for (int kb = 0; kb < SS/128; kb++) {
        cp_wait0();
        __syncthreads();
        if (kb + 1 < SS/128) {
            cp_kv(kb + 1, (kb + 1) & 1);
            if (tid < 128)
                maskf[((kb+1)&1)*128 + tid] =
                    (mask[b*SS + (kb+1)*128 + tid] != 0) ? 1.f : 0.f;
        }
        const uint32_t Kbuf = sb + AT_KV(kb & 1);
        const uint32_t Vbuf = sb + AT_VOFF(kb & 1);
        const float*   mk   = maskf + (kb & 1)*128;

        // ---- S = Q K^T (single product) ----
        float S[16][4];
#pragma unroll
        for (int t = 0; t < 16; t++)
#pragma unroll
            for (int u = 0; u < 4; u++) S[t][u] = 0.f;

#pragma unroll
        for (int p = 0; p < 8; p++) {
#pragma unroll
            for (int c = 0; c < 4; c++) {
                int n = 16*p + (lane & 7) + ((lane >> 4) & 1)*8;
                int k = c*16 + ((lane >> 3) & 1)*8;
                uint32_t r4[4], b0[2], b1[2];
                ldsm_x4(Kbuf + (uint32_t)(n*AT_ROW + k)*2, r4);
                b0[0]=r4[0]; b0[1]=r4[1]; b1[0]=r4[2]; b1[1]=r4[3];
                mma_bf16(S[2*p],   qf[c], b0);
                mma_bf16(S[2*p+1], qf[c], b1);
            }
        }

        // ---- u = mask * expm1(s) ----
#pragma unroll
        for (int t = 0; t < 16; t++) {
            int c0 = t*8 + (lane & 3)*2;
            float m0 = mk[c0], m1 = mk[c0 + 1];
            float u0 = m0 * expm1_poly(S[t][0]);
            float u1 = m1 * expm1_poly(S[t][1]);
            float u2 = m0 * expm1_poly(S[t][2]);
            float u3 = m1 * expm1_poly(S[t][3]);
            S[t][0] = u0; S[t][1] = u1; S[t][2] = u2; S[t][3] = u3;
            l0 += u0 + u1;
            l1 += u2 + u3;
        }

        // ---- O += U @ V via trans-ldmatrix B fragments ----
#pragma unroll
        for (int kc = 0; kc < 8; kc++) {
            uint32_t ua[4];
#pragma unroll
            for (int j = 0; j < 4; j++) {
                int t = 2*kc + (j >> 1);
                ua[j] = pack_bf16x2(S[t][(j & 1)*2 + 0], S[t][(j & 1)*2 + 1]);
            }
#pragma unroll
            for (int np = 0; np < 4; np++) {
                int rs = kc*16 + (lane & 7) + ((lane >> 3) & 1)*8;   // key (k)
                int cd = np*16 + ((lane >> 4) & 1)*8;                // dim (n)
                uint32_t r4[4], b0[2], b1[2];
                ldsm_x4_t(Vbuf + (uint32_t)(rs*AT_ROW + cd)*2, r4);
                b0[0]=r4[0]; b0[1]=r4[1]; b1[0]=r4[2]; b1[1]=r4[3];
                mma_bf16(O[2*np],   ua, b0);
                mma_bf16(O[2*np+1], ua, b1);
            }
        }
    }

    // ---- finalize ----
#pragma unroll
    for (int off = 1; off <= 2; off <<= 1) {
        l0 += __shfl_xor_sync(0xffffffffu, l0, off);
        l1 += __shfl_xor_sync(0xffffffffu, l1, off);
    }
    float msum = Msum[b];
    float inv0 = 1.f / (msum + l0), inv1 = 1.f / (msum + l1);

    int r0 = q0 + wid*16 + (lane >> 2);
    int r1 = r0 + 8;
#pragma unroll
    for (int nt = 0; nt < 8; nt++) {
        int dcol = nt*8 + (lane & 3)*2;
        float2 mv = *(const float2*)(Mv + b*EDIM + h*DD + dcol);
        float v0 = (O[nt][0] + mv.x) * inv0;
        float v1 = (O[nt][1] + mv.y) * inv0;
        float v2 = (O[nt][2] + mv.x) * inv1;
        float v3 = (O[nt][3] + mv.y) * inv1;
        size_t o0 = (size_t)(b*SS + r0)*EDIM + h*DD + dcol;
        size_t o1 = (size_t)(b*SS + r1)*EDIM + h*DD + dcol;
        uint32_t h0 = pack_bf16x2(v0, v1), h1 = pack_bf16x2(v2, v3);
        *(uint32_t*)(Ch + o0) = h0;
        *(uint32_t*)(Ch + o1) = h1;
        float f0 = __uint_as_float(h0 << 16);
        float f1 = __uint_as_float(h0 & 0xffff0000u);
        float f2 = __uint_as_float(h1 << 16);
        float f3 = __uint_as_float(h1 & 0xffff0000u);
        *(uint32_t*)(Cl + o0) = pack_bf16x2(v0 - f0, v1 - f1);
        *(uint32_t*)(Cl + o1) = pack_bf16x2(v2 - f2, v3 - f3);
    }
}

// ---------------- launch ----------------------------------------------------
extern "C" void kernel_launch(void* const* d_in, const int* in_sizes, int n_in,
                              void* d_out, int out_size)
{
    const float* q        = (const float*)d_in[0];
    const float* k        = (const float*)d_in[1];
    const float* v        = (const float*)d_in[2];
    const float* Wq       = (const float*)d_in[3];
    const float* bq       = (const float*)d_in[4];
    const float* Wk       = (const float*)d_in[5];
    const float* bk       = (const float*)d_in[6];
    const float* Wv_share = (const float*)d_in[7];
    const float* Wv_spec  = (const float*)d_in[8];
    const float* bv_share = (const float*)d_in[9];
    const float* bv_spec  = (const float*)d_in[10];
    const float* Wo_share = (const float*)d_in[11];
    const float* Wo_spec  = (const float*)d_in[12];
    const float* bo_share = (const float*)d_in[13];
    const float* bo_spec  = (const float*)d_in[14];
    const int*   mask     = (const int*)d_in[15];
    const int*   langp    = (const int*)d_in[16];
    float*       out      = (float*)d_out;

    bf16 *pqh,*pkh,*pvh,*pvl;
    bf16 *pWqh,*pWkh,*pWvh,*pWvl,*pWoh,*pWol;
    bf16 *pQh,*pKh,*pVh,*pVl,*pCh,*pCl;
    float *pbv,*pbo,*pMv,*pMs;
    cudaGetSymbolAddress((void**)&pqh, g_qh);
    cudaGetSymbolAddress((void**)&pkh, g_kh);
    cudaGetSymbolAddress((void**)&pvh, g_vh);  cudaGetSymbolAddress((void**)&pvl, g_vl);
    cudaGetSymbolAddress((void**)&pWqh, g_Wqh);
    cudaGetSymbolAddress((void**)&pWkh, g_Wkh);
    cudaGetSymbolAddress((void**)&pWvh, g_Wvh); cudaGetSymbolAddress((void**)&pWvl, g_Wvl);
    cudaGetSymbolAddress((void**)&pWoh, g_Woh); cudaGetSymbolAddress((void**)&pWol, g_Wol);
    cudaGetSymbolAddress((void**)&pQh, g_Qh);  cudaGetSymbolAddress((void**)&pKh, g_Kh);
    cudaGetSymbolAddress((void**)&pVh, g_Vh);  cudaGetSymbolAddress((void**)&pVl, g_Vl);
    cudaGetSymbolAddress((void**)&pCh, g_Ch);  cudaGetSymbolAddress((void**)&pCl, g_Cl);
    cudaGetSymbolAddress((void**)&pbv, g_bv);  cudaGetSymbolAddress((void**)&pbo, g_bo);
    cudaGetSymbolAddress((void**)&pMv, g_Mv);  cudaGetSymbolAddress((void**)&pMs, g_Msum);

    const int DS3 = 3*4*GS_ARRB;   // 122880
    const int DS1 = 3*2*GS_ARRB;   // 61440
    cudaFuncSetAttribute(attn_mma,
                         cudaFuncAttributeMaxDynamicSharedMemorySize, ATTN_SMEM);
    cudaFuncSetAttribute(gemm_mma<0,3>,
                         cudaFuncAttributeMaxDynamicSharedMemorySize, DS3);
    cudaFuncSetAttribute(gemm_mma<2,3>,
                         cudaFuncAttributeMaxDynamicSharedMemorySize, DS3);
    cudaFuncSetAttribute(gemm_qk,
                         cudaFuncAttributeMaxDynamicSharedMemorySize, DS1);

    // 1. consolidated prep (splits + weight fuse + masked v column sums)
    prep_kernel<<<PREP_BLKS, 256>>>(q, k, v, Wq, Wk, Wv_share, Wv_spec,
                                    bv_share, bv_spec, Wo_share, Wo_spec,
                                    bo_share, bo_spec, mask, langp);

    // 2. Mv = vsum @ Wv^T + cnt*bv  (off the V-GEMM critical path)
    dim3 gmv(EDIM/128, BB);
    mv_gemm<<<gmv, 128>>>();

    // 3. Q+K projections (batched), then V projection
    dim3 gqk(EDIM/128, MTOT/128, 2);
    gemm_qk<<<gqk, 256, DS1>>>(pqh, pkh, pWqh, pWkh, bq, bk, pQh, pKh);
    dim3 gg(EDIM/128, MTOT/128);
    gemm_mma<2,3><<<gg, 256, DS3>>>(pvh, pvl, pWvh, pWvl, pbv, 1.0f,
                                    nullptr, pVh, pVl);

    // 4. attention -> C (bf16 hi/lo)
    dim3 ga(SS/128, HH, BB);
    attn_mma<<<ga, 256, ATTN_SMEM>>>(pQh, pKh, pVh, mask, pMv, pMs, pCh, pCl);

    // 5. output projection -> d_out (fp32)
    gemm_mma<0,3><<<gg, 256, DS3>>>(pCh, pCl, pWoh, pWol, pbo, 1.0f,
                                    out, nullptr, nullptr);
}

// round 12
// speedup vs baseline: 1.3532x; 1.3532x over previous
#include <cuda_runtime.h>
#include <cuda_bf16.h>
#include <cstdint>

// Problem dims
#define EDIM 512
#define BB   16
#define SS   1024
#define HH   8
#define DD   64
#define MTOT (BB*SS)   // 16384
#define LL   4

typedef __nv_bfloat16 bf16;

// ---------------- scratch (device globals; no allocation allowed) ----------
__device__ bf16 g_qh[(size_t)MTOT*EDIM];
__device__ bf16 g_kh[(size_t)MTOT*EDIM];
__device__ bf16 g_vh[(size_t)MTOT*EDIM], g_vl[(size_t)MTOT*EDIM];
__device__ bf16 g_Wqh[EDIM*EDIM];
__device__ bf16 g_Wkh[EDIM*EDIM];
__device__ bf16 g_Wvh[EDIM*EDIM], g_Wvl[EDIM*EDIM];
__device__ bf16 g_Woh[EDIM*EDIM], g_Wol[EDIM*EDIM];
__device__ float g_bv[EDIM], g_bo[EDIM];
__device__ bf16 g_Qh[(size_t)MTOT*EDIM];           // projected Q (hi only)
__device__ bf16 g_Kh[(size_t)MTOT*EDIM];           // projected K (hi only)
__device__ bf16 g_Vh[(size_t)MTOT*EDIM], g_Vl[(size_t)MTOT*EDIM];
__device__ bf16 g_Ch[(size_t)MTOT*EDIM], g_Cl[(size_t)MTOT*EDIM];
__device__ float g_MvPart[BB*8*EDIM];
__device__ float g_MsPart[BB*8];
__device__ float g_Mv[BB*EDIM];
__device__ float g_Msum[BB];

// ======================= helpers ===========================================
__device__ __forceinline__ uint32_t smem_u32(const void* p) {
    uint32_t a;
    asm("{ .reg .u64 t; cvta.to.shared.u64 t, %1; cvt.u32.u64 %0, t; }"
        : "=r"(a) : "l"(p));
    return a;
}

__device__ __forceinline__ void ldsm_x4(uint32_t addr, uint32_t r[4]) {
    asm volatile("ldmatrix.sync.aligned.m8n8.x4.shared.b16 {%0,%1,%2,%3}, [%4];"
        : "=r"(r[0]), "=r"(r[1]), "=r"(r[2]), "=r"(r[3]) : "r"(addr));
}

__device__ __forceinline__ void ldsm_x4_t(uint32_t addr, uint32_t r[4]) {
    asm volatile("ldmatrix.sync.aligned.m8n8.x4.trans.shared.b16 {%0,%1,%2,%3}, [%4];"
        : "=r"(r[0]), "=r"(r[1]), "=r"(r[2]), "=r"(r[3]) : "r"(addr));
}

__device__ __forceinline__ void mma_bf16(float d[4], const uint32_t a[4],
                                         const uint32_t b[2]) {
    asm volatile(
        "mma.sync.aligned.m16n8k16.row.col.f32.bf16.bf16.f32 "
        "{%0,%1,%2,%3}, {%4,%5,%6,%7}, {%8,%9}, {%0,%1,%2,%3};"
        : "+f"(d[0]), "+f"(d[1]), "+f"(d[2]), "+f"(d[3])
        : "r"(a[0]), "r"(a[1]), "r"(a[2]), "r"(a[3]), "r"(b[0]), "r"(b[1]));
}

__device__ __forceinline__ uint32_t pack_bf16x2(float lo, float hi) {
    uint32_t r;
    asm("cvt.rn.bf16x2.f32 %0, %1, %2;" : "=r"(r) : "f"(hi), "f"(lo));
    return r;
}

__device__ __forceinline__ void split1(float x, bf16& h, bf16& l) {
    h = __float2bfloat16_rn(x);
    l = __float2bfloat16_rn(x - __bfloat162float(h));
}

__device__ __forceinline__ void split_pack4(const float4 v, uint2& hi, uint2& lo) {
    bf16 hx, hy, hz, hw, lx, ly, lz, lw;
    split1(v.x, hx, lx); split1(v.y, hy, ly);
    split1(v.z, hz, lz); split1(v.w, hw, lw);
    __nv_bfloat162 h01 = __nv_bfloat162(hx, hy), h23 = __nv_bfloat162(hz, hw);
    __nv_bfloat162 l01 = __nv_bfloat162(lx, ly), l23 = __nv_bfloat162(lz, lw);
    hi.x = *(uint32_t*)&h01; hi.y = *(uint32_t*)&h23;
    lo.x = *(uint32_t*)&l01; lo.y = *(uint32_t*)&l23;
}

// expm1(x) for |x| <~ 0.5
__device__ __forceinline__ float expm1_poly(float x) {
    float c = 8.33333333e-3f;
    c = fmaf(c, x, 4.16666667e-2f);
    c = fmaf(c, x, 1.66666667e-1f);
    c = fmaf(c, x, 0.5f);
    c = fmaf(c, x, 1.0f);
    return x * c;
}

__device__ __forceinline__ void cp16(uint32_t dst, const void* src) {
    asm volatile("cp.async.cg.shared.global [%0], [%1], 16;"
                 :: "r"(dst), "l"(src) : "memory");
}
__device__ __forceinline__ void cp_commit() {
    asm volatile("cp.async.commit_group;" ::: "memory");
}
__device__ __forceinline__ void cp_wait0() {
    asm volatile("cp.async.wait_group 0;" ::: "memory");
}
__device__ __forceinline__ void cp_wait1() {
    asm volatile("cp.async.wait_group 1;" ::: "memory");
}

// ---------------- merged input splits (uniform blocks, no tail) ------------
// blocks [0,8192): q->hi | [8192,16384): k->hi | [16384,24576): v->hi/lo
__global__ __launch_bounds__(256) void split3_kernel(
    const float* __restrict__ q, const float* __restrict__ k,
    const float* __restrict__ v)
{
    const int blk = blockIdx.x;
    const int which = blk >> 13;
    size_t i = ((size_t)(blk & 8191))*256 + threadIdx.x;
    const float* src = (which == 0) ? q : (which == 1) ? k : v;
    float4 val = *(const float4*)(src + i*4);
    uint2 h, l;
    split_pack4(val, h, l);
    if (which == 0)      *(uint2*)(g_qh + i*4) = h;
    else if (which == 1) *(uint2*)(g_kh + i*4) = h;
    else { *(uint2*)(g_vh + i*4) = h; *(uint2*)(g_vl + i*4) = l; }
}

// ---------------- weight fusion + split ------------------------------------
__global__ __launch_bounds__(256) void fuse_weights_kernel(
    const float* __restrict__ Wq, const float* __restrict__ Wk,
    const float* __restrict__ Wvs, const float* __restrict__ Wvp,
    const float* __restrict__ bvs, const float* __restrict__ bvp,
    const float* __restrict__ Wos, const float* __restrict__ Wop,
    const float* __restrict__ bos, const float* __restrict__ bop,
    const int*  __restrict__ langp)
{
    int lang = langp[0];
    if (lang < 0 || lang >= LL) {
        float f = __int_as_float(lang);
        int li = (int)f;
        lang = (li >= 0 && li < LL) ? li : 0;
    }
    int i = blockIdx.x * blockDim.x + threadIdx.x;
    if (i < EDIM*EDIM) {
        size_t off = (size_t)lang * EDIM * EDIM + i;
        g_Wqh[i] = __float2bfloat16_rn(Wq[i]);
        g_Wkh[i] = __float2bfloat16_rn(Wk[i]);
        split1(Wvs[i] * Wvp[off], g_Wvh[i], g_Wvl[i]);
        split1(Wos[i] * Wop[off], g_Woh[i], g_Wol[i]);
    }
    if (i < EDIM) {
        g_bv[i] = bvs[i] + bvp[lang*EDIM + i];
        g_bo[i] = bos[i] + bop[lang*EDIM + i];
    }
}

// ---------------- masked column sums of V (2-phase, deterministic) ---------
__global__ __launch_bounds__(512) void mv1_kernel(const int* __restrict__ mask)
{
    const int sc = blockIdx.x, b = blockIdx.y, d = threadIdx.x;
    float acc = 0.f;
    const int s0 = b*SS + sc*128;
#pragma unroll 4
    for (int s = 0; s < 128; s++) {
        if (mask[s0 + s] != 0) {
            size_t o = (size_t)(s0 + s)*EDIM + d;
            acc += __bfloat162float(g_Vh[o]) + __bfloat162float(g_Vl[o]);
        }
    }
    g_MvPart[(b*8 + sc)*EDIM + d] = acc;
    if (d == 0) {
        int c = 0;
        for (int s = 0; s < 128; s++) c += (mask[s0 + s] != 0);
        g_MsPart[b*8 + sc] = (float)c;
    }
}

__global__ __launch_bounds__(512) void mv2_kernel()
{
    const int b = blockIdx.x, d = threadIdx.x;
    float acc = 0.f;
#pragma unroll
    for (int sc = 0; sc < 8; sc++) acc += g_MvPart[(b*8 + sc)*EDIM + d];
    g_Mv[b*EDIM + d] = acc;
    if (d == 0) {
        float c = 0.f;
#pragma unroll
        for (int sc = 0; sc < 8; sc++) c += g_MsPart[b*8 + sc];
        g_Msum[b] = c;
    }
}

// =================== cp.async bf16 GEMM ====================================
// MODE 0: fp32 out; 1: bf16 hi only; 2: bf16 hi+lo.
// NPROD 3: hi/lo operands, 3-product. NPROD 1: hi-only operands, 1 product.
// MINB: min blocks per SM for __launch_bounds__ (2 for the slim 1-product).
#define GS_ROW   40
#define GS_ARRB  10240                     // bytes per array per stage (128*40*2)

template<int MODE, int NPROD, int MINB>
__global__ __launch_bounds__(256, MINB) void gemm_mma(
    const bf16* __restrict__ Ahi, const bf16* __restrict__ Alo,
    const bf16* __restrict__ Bhi, const bf16* __restrict__ Blo,
    const float* __restrict__ bias, float scale,
    float* __restrict__ outF, bf16* __restrict__ outHi, bf16* __restrict__ outLo)
{
    extern __shared__ __align__(128) bf16 smem[];
    constexpr int NARR = (NPROD == 3) ? 4 : 2;
    constexpr uint32_t STAGEB = NARR * GS_ARRB;

    const int tid  = threadIdx.x;
    const int lane = tid & 31;
    const int wid  = tid >> 5;
    const int wm   = wid >> 1;
    const int wn   = wid & 1;
    const int m0   = blockIdx.y * 128;
    const int n0   = blockIdx.x * 128;

    const uint32_t sb = smem_u32(smem);

    auto cp_stage = [&](int ks, int buf) {
        uint32_t sbase = sb + (uint32_t)buf * STAGEB;
#pragma unroll
        for (int c8 = 0; c8 < NARR*2; c8++) {
            int j = c8*256 + tid;
            int arr = j >> 9, jj = j & 511;
            int row = jj >> 2, cc = jj & 3;
            const bf16* src;
            if (NPROD == 3) {
                if      (arr == 0) src = Ahi + (size_t)(m0+row)*EDIM + ks*32 + cc*8;
                else if (arr == 1) src = Alo + (size_t)(m0+row)*EDIM + ks*32 + cc*8;
                else if (arr == 2) src = Bhi + (size_t)(n0+row)*EDIM + ks*32 + cc*8;
                else               src = Blo + (size_t)(n0+row)*EDIM + ks*32 + cc*8;
            } else {
                src = (arr == 0) ? Ahi + (size_t)(m0+row)*EDIM + ks*32 + cc*8
                                 : Bhi + (size_t)(n0+row)*EDIM + ks*32 + cc*8;
            }
            uint32_t dst = sbase + (uint32_t)arr*GS_ARRB + (uint32_t)(row*GS_ROW + cc*8)*2;
            cp16(dst, src);
        }
        cp_commit();
    };

    float d[2][8][4];
#pragma unroll
    for (int mt = 0; mt < 2; mt++)
#pragma unroll
        for (int nt = 0; nt < 8; nt++)
#pragma unroll
            for (int u = 0; u < 4; u++) d[mt][nt][u] = 0.f;

    cp_stage(0, 0);
    cp_stage(1, 1);

    for (int ks = 0; ks < 16; ks++) {
        if (ks < 15) cp_wait1(); else cp_wait0();
        __syncthreads();
        if (ks + 2 < 16) cp_stage(ks + 2, (ks + 2) % 3);

        const uint32_t base = sb + (uint32_t)(ks % 3) * STAGEB;
        const uint32_t aHi = base;
        const uint32_t aLo = base + GS_ARRB;
        const uint32_t bHi = base + (NPROD == 3 ? 2 : 1)*GS_ARRB;
        const uint32_t bLo = base + 3*GS_ARRB;

#pragma unroll
        for (int kk = 0; kk < 2; kk++) {
            const int kc = kk * 16;
            uint32_t ah[2][4], al[2][4];
            {
                int r = wm*32 + (lane & 7) + ((lane >> 3) & 1)*8;
                int k = kc + ((lane >> 4) & 1)*8;
                uint32_t off = (uint32_t)(r*GS_ROW + k)*2;
#pragma unroll
                for (int mt = 0; mt < 2; mt++) {
                    ldsm_x4(aHi + off + (uint32_t)(mt*16*GS_ROW)*2, ah[mt]);
                    if (NPROD == 3)
                        ldsm_x4(aLo + off + (uint32_t)(mt*16*GS_ROW)*2, al[mt]);
                }
            }
            uint32_t bh[8][2], bl[8][2];
            {
                int n = wn*64 + (lane & 7) + ((lane >> 4) & 1)*8;
                int k = kc + ((lane >> 3) & 1)*8;
                uint32_t off = (uint32_t)(n*GS_ROW + k)*2;
#pragma unroll
                for (int q = 0; q < 4; q++) {
                    uint32_t r4[4];
                    ldsm_x4(bHi + off + (uint32_t)(q*16*GS_ROW)*2, r4);
                    bh[2*q][0] = r4[0]; bh[2*q][1] = r4[1];
                    bh[2*q+1][0] = r4[2]; bh[2*q+1][1] = r4[3];
                    if (NPROD == 3) {
                        ldsm_x4(bLo + off + (uint32_t)(q*16*GS_ROW)*2, r4);
                        bl[2*q][0] = r4[0]; bl[2*q][1] = r4[1];
                        bl[2*q+1][0] = r4[2]; bl[2*q+1][1] = r4[3];
                    }
                }
            }
#pragma unroll
            for (int mt = 0; mt < 2; mt++)
#pragma unroll
                for (int nt = 0; nt < 8; nt++) {
                    mma_bf16(d[mt][nt], ah[mt], bh[nt]);
                    if (NPROD == 3) {
                        mma_bf16(d[mt][nt], ah[mt], bl[nt]);
                        mma_bf16(d[mt][nt], al[mt], bh[nt]);
                    }
                }
        }
    }

    // ---------------- epilogue --------------------------------------------
#pragma unroll
    for (int mt = 0; mt < 2; mt++) {
        int row0 = m0 + wm*32 + mt*16 + (lane >> 2);
#pragma unroll
        for (int nt = 0; nt < 8; nt++) {
            int col = n0 + wn*64 + nt*8 + (lane & 3)*2;
            float b0 = bias[col], b1 = bias[col + 1];
            float v0 = (d[mt][nt][0] + b0) * scale;
            float v1 = (d[mt][nt][1] + b1) * scale;
            float v2 = (d[mt][nt][2] + b0) * scale;
            float v3 = (d[mt][nt][3] + b1) * scale;
            size_t o0 = (size_t)row0*EDIM + col;
            size_t o1 = (size_t)(row0 + 8)*EDIM + col;
            if (MODE == 0) {
                *(float2*)(outF + o0) = make_float2(v0, v1);
                *(float2*)(outF + o1) = make_float2(v2, v3);
            } else {
                uint32_t h0 = pack_bf16x2(v0, v1), h1 = pack_bf16x2(v2, v3);
                *(uint32_t*)(outHi + o0) = h0;
                *(uint32_t*)(outHi + o1) = h1;
                if (MODE == 2) {
                    float f0 = __uint_as_float(h0 << 16);
                    float f1 = __uint_as_float(h0 & 0xffff0000u);
                    float f2 = __uint_as_float(h1 << 16);
                    float f3 = __uint_as_float(h1 & 0xffff0000u);
                    *(uint32_t*)(outLo + o0) = pack_bf16x2(v0 - f0, v1 - f1);
                    *(uint32_t*)(outLo + o1) = pack_bf16x2(v2 - f2, v3 - f3);
                }
            }
        }
    }
}

// =================== attention: single-bf16 QK, trans-ldmatrix PV ==========
#define AT_ROW   72
#define AT_QOFF  0
#define AT_KV(buf)   (18432 + (buf)*36864)
#define AT_VOFF(buf) (AT_KV(buf) + 18432)
#define AT_MASK  92160
#define ATTN_SMEM (92160 + 1024)

__global__ __launch_bounds__(256, 1) void attn_mma(
    const bf16* __restrict__ Qh, const bf16* __restrict__ Kh,
    const bf16* __restrict__ Vh, const int* __restrict__ mask,
    const float* __restrict__ Mv, const float* __restrict__ Msum,
    bf16* __restrict__ Ch, bf16* __restrict__ Cl)
{
    extern __shared__ __align__(128) bf16 sm[];

    const int tid  = threadIdx.x;
    const int lane = tid & 31;
    const int wid  = tid >> 5;
    const int b    = blockIdx.z, h = blockIdx.y;
    const int q0   = blockIdx.x * 128;

    const uint32_t sb = smem_u32(sm);
    float* maskf = (float*)((char*)sm + AT_MASK);   // [2][128]

    auto cp_kv = [&](int kb, int buf) {
#pragma unroll
        for (int c8 = 0; c8 < 8; c8++) {
            int j = c8*256 + tid;
            int arr = j >> 10, jj = j & 1023;
            int row = jj >> 3, cc = jj & 7;
            const bf16* src = (arr ? Vh : Kh)
                + (size_t)(b*SS + kb*128 + row)*EDIM + h*DD + cc*8;
            uint32_t dst = sb + (arr ? AT_VOFF(buf) : AT_KV(buf))
                + (uint32_t)(row*AT_ROW + cc*8)*2;
            cp16(dst, src);
        }
        cp_commit();
    };

    // ---- Q tile (plain loads) + mask buf0 ----
#pragma unroll
    for (int c4 = 0; c4 < 4; c4++) {
        int j = c4*256 + tid;
        int row = j >> 3, cc = j & 7;
        uint4 v = *(const uint4*)(Qh + (size_t)(b*SS + q0 + row)*EDIM + h*DD + cc*8);
        uint32_t dst = sb + AT_QOFF + (uint32_t)(row*AT_ROW + cc*8)*2;
        asm volatile("st.shared.v4.b32 [%0], {%1,%2,%3,%4};"
                     :: "r"(dst), "r"(v.x), "r"(v.y), "r"(v.z), "r"(v.w));
    }
    if (tid < 128) maskf[tid] = (mask[b*SS + tid] != 0) ? 1.f : 0.f;
    cp_kv(0, 0);
    __syncthreads();

    // ---- Q fragments (single bf16) ----
    uint32_t qf[4][4];
    {
        int r = wid*16 + (lane & 7) + ((lane >> 3) & 1)*8;
#pragma unroll
        for (int kc = 0; kc < 4; kc++) {
            int k = kc*16 + ((lane >> 4) & 1)*8;
            ldsm_x4(sb + AT_QOFF + (uint32_t)(r*AT_ROW + k)*2, qf[kc]);
        }
    }

    float l0 = 0.f, l1 = 0.f;
    float O[8][4];
#pragma unroll
    for (int nt = 0; nt < 8; nt++)
#pragma unroll
        for (int u = 0; u < 4; u++) O[nt][u] = 0.f;

    for (int kb = 0; kb < SS/128; kb++) {
        cp_wait0();
        __syncthreads();
        if (kb + 1 < SS/128) {
            cp_kv(kb + 1, (kb + 1) & 1);
            if (tid < 128)
                maskf[((kb+1)&1)*128 + tid] =
                    (mask[b*SS + (kb+1)*128 + tid] != 0) ? 1.f : 0.f;
        }
        const uint32_t Kbuf = sb + AT_KV(kb & 1);
        const uint32_t Vbuf = sb + AT_VOFF(kb & 1);
        const float*   mk   = maskf + (kb & 1)*128;

        // ---- S = Q K^T (single product) ----
        float S[16][4];
#pragma unroll
        for (int t = 0; t < 16; t++)
#pragma unroll
            for (int u = 0; u < 4; u++) S[t][u] = 0.f;

#pragma unroll
        for (int p = 0; p < 8; p++) {
#pragma unroll
            for (int c = 0; c < 4; c++) {
                int n = 16*p + (lane & 7) + ((lane >> 4) & 1)*8;
                int k = c*16 + ((lane >> 3) & 1)*8;
                uint32_t r4[4], b0[2], b1[2];
                ldsm_x4(Kbuf + (uint32_t)(n*AT_ROW + k)*2, r4);
                b0[0]=r4[0]; b0[1]=r4[1]; b1[0]=r4[2]; b1[1]=r4[3];
                mma_bf16(S[2*p],   qf[c], b0);
                mma_bf16(S[2*p+1], qf[c], b1);
            }
        }

        // ---- u = mask * expm1(s) ----
#pragma unroll
        for (int t = 0; t < 16; t++) {
            int c0 = t*8 + (lane & 3)*2;
            float m0 = mk[c0], m1 = mk[c0 + 1];
            float u0 = m0 * expm1_poly(S[t][0]);
            float u1 = m1 * expm1_poly(S[t][1]);
            float u2 = m0 * expm1_poly(S[t][2]);
            float u3 = m1 * expm1_poly(S[t][3]);
            S[t][0] = u0; S[t][1] = u1; S[t][2] = u2; S[t][3] = u3;
            l0 += u0 + u1;
            l1 += u2 + u3;
        }

        // ---- O += U @ V via trans-ldmatrix B fragments ----
#pragma unroll
        for (int kc = 0; kc < 8; kc++) {
            uint32_t ua[4];
#pragma unroll
            for (int j = 0; j < 4; j++) {
                int t = 2*kc + (j >> 1);
                ua[j] = pack_bf16x2(S[t][(j & 1)*2 + 0], S[t][(j & 1)*2 + 1]);
            }
#pragma unroll
            for (int np = 0; np < 4; np++) {
                int rs = kc*16 + (lane & 7) + ((lane >> 3) & 1)*8;   // key (k)
                int cd = np*16 + ((lane >> 4) & 1)*8;                // dim (n)
                uint32_t r4[4], b0[2], b1[2];
                ldsm_x4_t(Vbuf + (uint32_t)(rs*AT_ROW + cd)*2, r4);
                b0[0]=r4[0]; b0[1]=r4[1]; b1[0]=r4[2]; b1[1]=r4[3];
                mma_bf16(O[2*np],   ua, b0);
                mma_bf16(O[2*np+1], ua, b1);
            }
        }
    }

    // ---- finalize ----
#pragma unroll
    for (int off = 1; off <= 2; off <<= 1) {
        l0 += __shfl_xor_sync(0xffffffffu, l0, off);
        l1 += __shfl_xor_sync(0xffffffffu, l1, off);
    }
    float msum = Msum[b];
    float inv0 = 1.f / (msum + l0), inv1 = 1.f / (msum + l1);

    int r0 = q0 + wid*16 + (lane >> 2);
    int r1 = r0 + 8;
#pragma unroll
    for (int nt = 0; nt < 8; nt++) {
        int dcol = nt*8 + (lane & 3)*2;
        float2 mv = *(const float2*)(Mv + b*EDIM + h*DD + dcol);
        float v0 = (O[nt][0] + mv.x) * inv0;
        float v1 = (O[nt][1] + mv.y) * inv0;
        float v2 = (O[nt][2] + mv.x) * inv1;
        float v3 = (O[nt][3] + mv.y) * inv1;
        size_t o0 = (size_t)(b*SS + r0)*EDIM + h*DD + dcol;
        size_t o1 = (size_t)(b*SS + r1)*EDIM + h*DD + dcol;
        uint32_t h0 = pack_bf16x2(v0, v1), h1 = pack_bf16x2(v2, v3);
        *(uint32_t*)(Ch + o0) = h0;
        *(uint32_t*)(Ch + o1) = h1;
        float f0 = __uint_as_float(h0 << 16);
        float f1 = __uint_as_float(h0 & 0xffff0000u);
        float f2 = __uint_as_float(h1 << 16);
        float f3 = __uint_as_float(h1 & 0xffff0000u);
        *(uint32_t*)(Cl + o0) = pack_bf16x2(v0 - f0, v1 - f1);
        *(uint32_t*)(Cl + o1) = pack_bf16x2(v2 - f2, v3 - f3);
    }
}

// ---------------- launch ----------------------------------------------------
extern "C" void kernel_launch(void* const* d_in, const int* in_sizes, int n_in,
                              void* d_out, int out_size)
{
    const float* q        = (const float*)d_in[0];
    const float* k        = (const float*)d_in[1];
    const float* v        = (const float*)d_in[2];
    const float* Wq       = (const float*)d_in[3];
    const float* bq       = (const float*)d_in[4];
    const float* Wk       = (const float*)d_in[5];
    const float* bk       = (const float*)d_in[6];
    const float* Wv_share = (const float*)d_in[7];
    const float* Wv_spec  = (const float*)d_in[8];
    const float* bv_share = (const float*)d_in[9];
    const float* bv_spec  = (const float*)d_in[10];
    const float* Wo_share = (const float*)d_in[11];
    const float* Wo_spec  = (const float*)d_in[12];
    const float* bo_share = (const float*)d_in[13];
    const float* bo_spec  = (const float*)d_in[14];
    const int*   mask     = (const int*)d_in[15];
    const int*   langp    = (const int*)d_in[16];
    float*       out      = (float*)d_out;

    bf16 *pqh,*pkh,*pvh,*pvl;
    bf16 *pWqh,*pWkh,*pWvh,*pWvl,*pWoh,*pWol;
    bf16 *pQh,*pKh,*pVh,*pVl,*pCh,*pCl;
    float *pbv,*pbo,*pMv,*pMs;
    cudaGetSymbolAddress((void**)&pqh, g_qh);
    cudaGetSymbolAddress((void**)&pkh, g_kh);
    cudaGetSymbolAddress((void**)&pvh, g_vh);  cudaGetSymbolAddress((void**)&pvl, g_vl);
    cudaGetSymbolAddress((void**)&pWqh, g_Wqh);
    cudaGetSymbolAddress((void**)&pWkh, g_Wkh);
    cudaGetSymbolAddress((void**)&pWvh, g_Wvh); cudaGetSymbolAddress((void**)&pWvl, g_Wvl);
    cudaGetSymbolAddress((void**)&pWoh, g_Woh); cudaGetSymbolAddress((void**)&pWol, g_Wol);
    cudaGetSymbolAddress((void**)&pQh, g_Qh);  cudaGetSymbolAddress((void**)&pKh, g_Kh);
    cudaGetSymbolAddress((void**)&pVh, g_Vh);  cudaGetSymbolAddress((void**)&pVl, g_Vl);
    cudaGetSymbolAddress((void**)&pCh, g_Ch);  cudaGetSymbolAddress((void**)&pCl, g_Cl);
    cudaGetSymbolAddress((void**)&pbv, g_bv);  cudaGetSymbolAddress((void**)&pbo, g_bo);
    cudaGetSymbolAddress((void**)&pMv, g_Mv);  cudaGetSymbolAddress((void**)&pMs, g_Msum);

    const int DS3 = 3*4*GS_ARRB;   // 122880
    const int DS1 = 3*2*GS_ARRB;   // 61440
    cudaFuncSetAttribute(attn_mma,
                         cudaFuncAttributeMaxDynamicSharedMemorySize, ATTN_SMEM);
    cudaFuncSetAttribute(gemm_mma<0,3,1>,
                         cudaFuncAttributeMaxDynamicSharedMemorySize, DS3);
    cudaFuncSetAttribute(gemm_mma<2,3,1>,
                         cudaFuncAttributeMaxDynamicSharedMemorySize, DS3);
    cudaFuncSetAttribute(gemm_mma<1,1,2>,
                         cudaFuncAttributeMaxDynamicSharedMemorySize, DS1);

    // 1. merged input splits + weight fuse/split
    split3_kernel<<<24576, 256>>>(q, k, v);
    fuse_weights_kernel<<<1024, 256>>>(Wq, Wk, Wv_share, Wv_spec, bv_share,
                                       bv_spec, Wo_share, Wo_spec, bo_share,
                                       bo_spec, langp);

    // 2. projections (Q folds the double 1/sqrt(D) = 1/64)
    dim3 gg(EDIM/128, MTOT/128);   // (4, 128)
    gemm_mma<1,1,2><<<gg, 256, DS1>>>(pqh, nullptr, pWqh, nullptr, bq, 1.0f/64.0f,
                                      nullptr, pQh, nullptr);
    gemm_mma<1,1,2><<<gg, 256, DS1>>>(pkh, nullptr, pWkh, nullptr, bk, 1.0f,
                                      nullptr, pKh, nullptr);
    gemm_mma<2,3,1><<<gg, 256, DS3>>>(pvh, pvl, pWvh, pWvl, pbv, 1.0f,
                                      nullptr, pVh, pVl);

    // 2b. masked column sums of V
    dim3 gm1(8, BB);
    mv1_kernel<<<gm1, 512>>>(mask);
    mv2_kernel<<<BB, 512>>>();

    // 3. attention -> C (bf16 hi/lo)
    dim3 ga(SS/128, HH, BB);
    attn_mma<<<ga, 256, ATTN_SMEM>>>(pQh, pKh, pVh, mask, pMv, pMs, pCh, pCl);

    // 4. output projection -> d_out (fp32)
    gemm_mma<0,3,1><<<gg, 256, DS3>>>(pCh, pCl, pWoh, pWol, pbo, 1.0f,
                                      out, nullptr, nullptr);
}

// round 13
// speedup vs baseline: 1.4126x; 1.0439x over previous
#include <cuda_runtime.h>
#include <cuda_bf16.h>
#include <cstdint>

// Problem dims
#define EDIM 512
#define BB   16
#define SS   1024
#define HH   8
#define DD   64
#define MTOT (BB*SS)   // 16384
#define LL   4

typedef __nv_bfloat16 bf16;

// ---------------- scratch (device globals; no allocation allowed) ----------
__device__ bf16 g_qh[(size_t)MTOT*EDIM];
__device__ bf16 g_kh[(size_t)MTOT*EDIM];
__device__ bf16 g_vh[(size_t)MTOT*EDIM], g_vl[(size_t)MTOT*EDIM];
__device__ bf16 g_Wqh[EDIM*EDIM];
__device__ bf16 g_Wkh[EDIM*EDIM];
__device__ bf16 g_Wvh[EDIM*EDIM], g_Wvl[EDIM*EDIM];
__device__ bf16 g_Woh[EDIM*EDIM], g_Wol[EDIM*EDIM];
__device__ float g_bv[EDIM], g_bo[EDIM];
__device__ bf16 g_Qh[(size_t)MTOT*EDIM];           // projected Q (hi only)
__device__ bf16 g_Kh[(size_t)MTOT*EDIM];           // projected K (hi, masked rows zeroed)
__device__ bf16 g_Vh[(size_t)MTOT*EDIM], g_Vl[(size_t)MTOT*EDIM];
__device__ bf16 g_Ch[(size_t)MTOT*EDIM], g_Cl[(size_t)MTOT*EDIM];
__device__ float g_MvPart[BB*8*EDIM];
__device__ float g_MsPart[BB*8];
__device__ float g_Mv[BB*EDIM];
__device__ float g_Msum[BB];

// ======================= helpers ===========================================
__device__ __forceinline__ uint32_t smem_u32(const void* p) {
    uint32_t a;
    asm("{ .reg .u64 t; cvta.to.shared.u64 t, %1; cvt.u32.u64 %0, t; }"
        : "=r"(a) : "l"(p));
    return a;
}

__device__ __forceinline__ void ldsm_x4(uint32_t addr, uint32_t r[4]) {
    asm volatile("ldmatrix.sync.aligned.m8n8.x4.shared.b16 {%0,%1,%2,%3}, [%4];"
        : "=r"(r[0]), "=r"(r[1]), "=r"(r[2]), "=r"(r[3]) : "r"(addr));
}

__device__ __forceinline__ void ldsm_x4_t(uint32_t addr, uint32_t r[4]) {
    asm volatile("ldmatrix.sync.aligned.m8n8.x4.trans.shared.b16 {%0,%1,%2,%3}, [%4];"
        : "=r"(r[0]), "=r"(r[1]), "=r"(r[2]), "=r"(r[3]) : "r"(addr));
}

__device__ __forceinline__ void mma_bf16(float d[4], const uint32_t a[4],
                                         const uint32_t b[2]) {
    asm volatile(
        "mma.sync.aligned.m16n8k16.row.col.f32.bf16.bf16.f32 "
        "{%0,%1,%2,%3}, {%4,%5,%6,%7}, {%8,%9}, {%0,%1,%2,%3};"
        : "+f"(d[0]), "+f"(d[1]), "+f"(d[2]), "+f"(d[3])
        : "r"(a[0]), "r"(a[1]), "r"(a[2]), "r"(a[3]), "r"(b[0]), "r"(b[1]));
}

__device__ __forceinline__ uint32_t pack_bf16x2(float lo, float hi) {
    uint32_t r;
    asm("cvt.rn.bf16x2.f32 %0, %1, %2;" : "=r"(r) : "f"(hi), "f"(lo));
    return r;
}

__device__ __forceinline__ void split1(float x, bf16& h, bf16& l) {
    h = __float2bfloat16_rn(x);
    l = __float2bfloat16_rn(x - __bfloat162float(h));
}

__device__ __forceinline__ void split_pack4(const float4 v, uint2& hi, uint2& lo) {
    bf16 hx, hy, hz, hw, lx, ly, lz, lw;
    split1(v.x, hx, lx); split1(v.y, hy, ly);
    split1(v.z, hz, lz); split1(v.w, hw, lw);
    __nv_bfloat162 h01 = __nv_bfloat162(hx, hy), h23 = __nv_bfloat162(hz, hw);
    __nv_bfloat162 l01 = __nv_bfloat162(lx, ly), l23 = __nv_bfloat162(lz, lw);
    hi.x = *(uint32_t*)&h01; hi.y = *(uint32_t*)&h23;
    lo.x = *(uint32_t*)&l01; lo.y = *(uint32_t*)&l23;
}

// expm1(x) for |x| <~ 0.5
__device__ __forceinline__ float expm1_poly(float x) {
    float c = 8.33333333e-3f;
    c = fmaf(c, x, 4.16666667e-2f);
    c = fmaf(c, x, 1.66666667e-1f);
    c = fmaf(c, x, 0.5f);
    c = fmaf(c, x, 1.0f);
    return x * c;
}

__device__ __forceinline__ void cp16(uint32_t dst, const void* src) {
    asm volatile("cp.async.cg.shared.global [%0], [%1], 16;"
                 :: "r"(dst), "l"(src) : "memory");
}
__device__ __forceinline__ void cp_commit() {
    asm volatile("cp.async.commit_group;" ::: "memory");
}
__device__ __forceinline__ void cp_wait0() {
    asm volatile("cp.async.wait_group 0;" ::: "memory");
}
__device__ __forceinline__ void cp_wait1() {
    asm volatile("cp.async.wait_group 1;" ::: "memory");
}

// ---------------- merged input splits (uniform blocks, no tail) ------------
__global__ __launch_bounds__(256) void split3_kernel(
    const float* __restrict__ q, const float* __restrict__ k,
    const float* __restrict__ v)
{
    const int blk = blockIdx.x;
    const int which = blk >> 13;
    size_t i = ((size_t)(blk & 8191))*256 + threadIdx.x;
    const float* src = (which == 0) ? q : (which == 1) ? k : v;
    float4 val = *(const float4*)(src + i*4);
    uint2 h, l;
    split_pack4(val, h, l);
    if (which == 0)      *(uint2*)(g_qh + i*4) = h;
    else if (which == 1) *(uint2*)(g_kh + i*4) = h;
    else { *(uint2*)(g_vh + i*4) = h; *(uint2*)(g_vl + i*4) = l; }
}

// ---------------- weight fusion + split ------------------------------------
__global__ __launch_bounds__(256) void fuse_weights_kernel(
    const float* __restrict__ Wq, const float* __restrict__ Wk,
    const float* __restrict__ Wvs, const float* __restrict__ Wvp,
    const float* __restrict__ bvs, const float* __restrict__ bvp,
    const float* __restrict__ Wos, const float* __restrict__ Wop,
    const float* __restrict__ bos, const float* __restrict__ bop,
    const int*  __restrict__ langp)
{
    int lang = langp[0];
    if (lang < 0 || lang >= LL) {
        float f = __int_as_float(lang);
        int li = (int)f;
        lang = (li >= 0 && li < LL) ? li : 0;
    }
    int i = blockIdx.x * blockDim.x + threadIdx.x;
    if (i < EDIM*EDIM) {
        size_t off = (size_t)lang * EDIM * EDIM + i;
        g_Wqh[i] = __float2bfloat16_rn(Wq[i]);
        g_Wkh[i] = __float2bfloat16_rn(Wk[i]);
        split1(Wvs[i] * Wvp[off], g_Wvh[i], g_Wvl[i]);
        split1(Wos[i] * Wop[off], g_Woh[i], g_Wol[i]);
    }
    if (i < EDIM) {
        g_bv[i] = bvs[i] + bvp[lang*EDIM + i];
        g_bo[i] = bos[i] + bop[lang*EDIM + i];
    }
}

// ---------------- masked column sums of V (2-phase, deterministic) ---------
__global__ __launch_bounds__(512) void mv1_kernel(const int* __restrict__ mask)
{
    const int sc = blockIdx.x, b = blockIdx.y, d = threadIdx.x;
    float acc = 0.f;
    const int s0 = b*SS + sc*128;
#pragma unroll 4
    for (int s = 0; s < 128; s++) {
        if (mask[s0 + s] != 0) {
            size_t o = (size_t)(s0 + s)*EDIM + d;
            acc += __bfloat162float(g_Vh[o]) + __bfloat162float(g_Vl[o]);
        }
    }
    g_MvPart[(b*8 + sc)*EDIM + d] = acc;
    if (d == 0) {
        int c = 0;
        for (int s = 0; s < 128; s++) c += (mask[s0 + s] != 0);
        g_MsPart[b*8 + sc] = (float)c;
    }
}

__global__ __launch_bounds__(512) void mv2_kernel()
{
    const int b = blockIdx.x, d = threadIdx.x;
    float acc = 0.f;
#pragma unroll
    for (int sc = 0; sc < 8; sc++) acc += g_MvPart[(b*8 + sc)*EDIM + d];
    g_Mv[b*EDIM + d] = acc;
    if (d == 0) {
        float c = 0.f;
#pragma unroll
        for (int sc = 0; sc < 8; sc++) c += g_MsPart[b*8 + sc];
        g_Msum[b] = c;
    }
}

// =================== cp.async bf16 GEMM ====================================
// MODE 0: fp32 out; 1: bf16 hi only; 2: bf16 hi+lo.
// NPROD 3: hi/lo operands, 3-product. NPROD 1: hi-only operands, 1 product.
// maskp != nullptr: zero output rows whose mask entry is 0 (K projection).
#define GS_ROW   40
#define GS_ARRB  10240                     // bytes per array per stage (128*40*2)

template<int MODE, int NPROD, int MINB>
__global__ __launch_bounds__(256, MINB) void gemm_mma(
    const bf16* __restrict__ Ahi, const bf16* __restrict__ Alo,
    const bf16* __restrict__ Bhi, const bf16* __restrict__ Blo,
    const float* __restrict__ bias, float scale,
    float* __restrict__ outF, bf16* __restrict__ outHi, bf16* __restrict__ outLo,
    const int* __restrict__ maskp)
{
    extern __shared__ __align__(128) bf16 smem[];
    constexpr int NARR = (NPROD == 3) ? 4 : 2;
    constexpr uint32_t STAGEB = NARR * GS_ARRB;

    const int tid  = threadIdx.x;
    const int lane = tid & 31;
    const int wid  = tid >> 5;
    const int wm   = wid >> 1;
    const int wn   = wid & 1;
    const int m0   = blockIdx.y * 128;
    const int n0   = blockIdx.x * 128;

    const uint32_t sb = smem_u32(smem);

    auto cp_stage = [&](int ks, int buf) {
        uint32_t sbase = sb + (uint32_t)buf * STAGEB;
#pragma unroll
        for (int c8 = 0; c8 < NARR*2; c8++) {
            int j = c8*256 + tid;
            int arr = j >> 9, jj = j & 511;
            int row = jj >> 2, cc = jj & 3;
            const bf16* src;
            if (NPROD == 3) {
                if      (arr == 0) src = Ahi + (size_t)(m0+row)*EDIM + ks*32 + cc*8;
                else if (arr == 1) src = Alo + (size_t)(m0+row)*EDIM + ks*32 + cc*8;
                else if (arr == 2) src = Bhi + (size_t)(n0+row)*EDIM + ks*32 + cc*8;
                else               src = Blo + (size_t)(n0+row)*EDIM + ks*32 + cc*8;
            } else {
                src = (arr == 0) ? Ahi + (size_t)(m0+row)*EDIM + ks*32 + cc*8
                                 : Bhi + (size_t)(n0+row)*EDIM + ks*32 + cc*8;
            }
            uint32_t dst = sbase + (uint32_t)arr*GS_ARRB + (uint32_t)(row*GS_ROW + cc*8)*2;
            cp16(dst, src);
        }
        cp_commit();
    };

    float d[2][8][4];
#pragma unroll
    for (int mt = 0; mt < 2; mt++)
#pragma unroll
        for (int nt = 0; nt < 8; nt++)
#pragma unroll
            for (int u = 0; u < 4; u++) d[mt][nt][u] = 0.f;

    cp_stage(0, 0);
    cp_stage(1, 1);

    for (int ks = 0; ks < 16; ks++) {
        if (ks < 15) cp_wait1(); else cp_wait0();
        __syncthreads();
        if (ks + 2 < 16) cp_stage(ks + 2, (ks + 2) % 3);

        const uint32_t base = sb + (uint32_t)(ks % 3) * STAGEB;
        const uint32_t aHi = base;
        const uint32_t aLo = base + GS_ARRB;
        const uint32_t bHi = base + (NPROD == 3 ? 2 : 1)*GS_ARRB;
        const uint32_t bLo = base + 3*GS_ARRB;

#pragma unroll
        for (int kk = 0; kk < 2; kk++) {
            const int kc = kk * 16;
            uint32_t ah[2][4], al[2][4];
            {
                int r = wm*32 + (lane & 7) + ((lane >> 3) & 1)*8;
                int k = kc + ((lane >> 4) & 1)*8;
                uint32_t off = (uint32_t)(r*GS_ROW + k)*2;
#pragma unroll
                for (int mt = 0; mt < 2; mt++) {
                    ldsm_x4(aHi + off + (uint32_t)(mt*16*GS_ROW)*2, ah[mt]);
                    if (NPROD == 3)
                        ldsm_x4(aLo + off + (uint32_t)(mt*16*GS_ROW)*2, al[mt]);
                }
            }
            uint32_t bh[8][2], bl[8][2];
            {
                int n = wn*64 + (lane & 7) + ((lane >> 4) & 1)*8;
                int k = kc + ((lane >> 3) & 1)*8;
                uint32_t off = (uint32_t)(n*GS_ROW + k)*2;
#pragma unroll
                for (int q = 0; q < 4; q++) {
                    uint32_t r4[4];
                    ldsm_x4(bHi + off + (uint32_t)(q*16*GS_ROW)*2, r4);
                    bh[2*q][0] = r4[0]; bh[2*q][1] = r4[1];
                    bh[2*q+1][0] = r4[2]; bh[2*q+1][1] = r4[3];
                    if (NPROD == 3) {
                        ldsm_x4(bLo + off + (uint32_t)(q*16*GS_ROW)*2, r4);
                        bl[2*q][0] = r4[0]; bl[2*q][1] = r4[1];
                        bl[2*q+1][0] = r4[2]; bl[2*q+1][1] = r4[3];
                    }
                }
            }
#pragma unroll
            for (int mt = 0; mt < 2; mt++)
#pragma unroll
                for (int nt = 0; nt < 8; nt++) {
                    mma_bf16(d[mt][nt], ah[mt], bh[nt]);
                    if (NPROD == 3) {
                        mma_bf16(d[mt][nt], ah[mt], bl[nt]);
                        mma_bf16(d[mt][nt], al[mt], bh[nt]);
                    }
                }
        }
    }

    // ---------------- epilogue --------------------------------------------
#pragma unroll
    for (int mt = 0; mt < 2; mt++) {
        int row0 = m0 + wm*32 + mt*16 + (lane >> 2);
        float mr0 = 1.f, mr1 = 1.f;
        if (maskp != nullptr) {
            mr0 = (maskp[row0] != 0) ? 1.f : 0.f;
            mr1 = (maskp[row0 + 8] != 0) ? 1.f : 0.f;
        }
#pragma unroll
        for (int nt = 0; nt < 8; nt++) {
            int col = n0 + wn*64 + nt*8 + (lane & 3)*2;
            float b0 = bias[col], b1 = bias[col + 1];
            float v0 = (d[mt][nt][0] + b0) * scale * mr0;
            float v1 = (d[mt][nt][1] + b1) * scale * mr0;
            float v2 = (d[mt][nt][2] + b0) * scale * mr1;
            float v3 = (d[mt][nt][3] + b1) * scale * mr1;
            size_t o0 = (size_t)row0*EDIM + col;
            size_t o1 = (size_t)(row0 + 8)*EDIM + col;
            if (MODE == 0) {
                *(float2*)(outF + o0) = make_float2(v0, v1);
                *(float2*)(outF + o1) = make_float2(v2, v3);
            } else {
                uint32_t h0 = pack_bf16x2(v0, v1), h1 = pack_bf16x2(v2, v3);
                *(uint32_t*)(outHi + o0) = h0;
                *(uint32_t*)(outHi + o1) = h1;
                if (MODE == 2) {
                    float f0 = __uint_as_float(h0 << 16);
                    float f1 = __uint_as_float(h0 & 0xffff0000u);
                    float f2 = __uint_as_float(h1 << 16);
                    float f3 = __uint_as_float(h1 & 0xffff0000u);
                    *(uint32_t*)(outLo + o0) = pack_bf16x2(v0 - f0, v1 - f1);
                    *(uint32_t*)(outLo + o1) = pack_bf16x2(v2 - f2, v3 - f3);
                }
            }
        }
    }
}

// =================== attention: interleaved QK/exp/PV, 2 CTAs/SM ===========
// Mask is pre-folded into K (masked rows zeroed -> s=0 -> expm1(s)=0).
// Per key-tile-pair p (16 keys): 8 QK mmas -> expm1 on 8 values -> pack ->
// 8 PV mmas. S live range = 8 regs instead of 64.
#define AT_ROW   72
#define AT_QOFF  0
#define AT_KV(buf)   (18432 + (buf)*36864)
#define AT_VOFF(buf) (AT_KV(buf) + 18432)
#define ATTN_SMEM 92160

__global__ __launch_bounds__(256, 2) void attn_mma(
    const bf16* __restrict__ Qh, const bf16* __restrict__ Kh,
    const bf16* __restrict__ Vh,
    const float* __restrict__ Mv, const float* __restrict__ Msum,
    bf16* __restrict__ Ch, bf16* __restrict__ Cl)
{
    extern __shared__ __align__(128) bf16 sm[];

    const int tid  = threadIdx.x;
    const int lane = tid & 31;
    const int wid  = tid >> 5;
    const int b    = blockIdx.z, h = blockIdx.y;
    const int q0   = blockIdx.x * 128;

    const uint32_t sb = smem_u32(sm);

    auto cp_kv = [&](int kb, int buf) {
#pragma unroll
        for (int c8 = 0; c8 < 8; c8++) {
            int j = c8*256 + tid;
            int arr = j >> 10, jj = j & 1023;
            int row = jj >> 3, cc = jj & 7;
            const bf16* src = (arr ? Vh : Kh)
                + (size_t)(b*SS + kb*128 + row)*EDIM + h*DD + cc*8;
            uint32_t dst = sb + (arr ? AT_VOFF(buf) : AT_KV(buf))
                + (uint32_t)(row*AT_ROW + cc*8)*2;
            cp16(dst, src);
        }
        cp_commit();
    };

    // ---- Q tile (plain loads) ----
#pragma unroll
    for (int c4 = 0; c4 < 4; c4++) {
        int j = c4*256 + tid;
        int row = j >> 3, cc = j & 7;
        uint4 v = *(const uint4*)(Qh + (size_t)(b*SS + q0 + row)*EDIM + h*DD + cc*8);
        uint32_t dst = sb + AT_QOFF + (uint32_t)(row*AT_ROW + cc*8)*2;
        asm volatile("st.shared.v4.b32 [%0], {%1,%2,%3,%4};"
                     :: "r"(dst), "r"(v.x), "r"(v.y), "r"(v.z), "r"(v.w));
    }
    cp_kv(0, 0);
    __syncthreads();

    // ---- Q fragments (single bf16) ----
    uint32_t qf[4][4];
    {
        int r = wid*16 + (lane & 7) + ((lane >> 3) & 1)*8;
#pragma unroll
        for (int kc = 0; kc < 4; kc++) {
            int k = kc*16 + ((lane >> 4) & 1)*8;
            ldsm_x4(sb + AT_QOFF + (uint32_t)(r*AT_ROW + k)*2, qf[kc]);
        }
    }

    float l0 = 0.f, l1 = 0.f;
    float O[8][4];
#pragma unroll
    for (int nt = 0; nt < 8; nt++)
#pragma unroll
        for (int u = 0; u < 4; u++) O[nt][u] = 0.f;

    for (int kb = 0; kb < SS/128; kb++) {
        cp_wait0();
        __syncthreads();
        if (kb + 1 < SS/128) cp_kv(kb + 1, (kb + 1) & 1);
        const uint32_t Kbuf = sb + AT_KV(kb & 1);
        const uint32_t Vbuf = sb + AT_VOFF(kb & 1);

#pragma unroll
        for (int p = 0; p < 8; p++) {       // 16-key tile pair == k16 chunk p
            // ---- S tile pair = Q K^T ----
            float S0[4] = {0.f, 0.f, 0.f, 0.f};
            float S1[4] = {0.f, 0.f, 0.f, 0.f};
#pragma unroll
            for (int c = 0; c < 4; c++) {
                int n = 16*p + (lane & 7) + ((lane >> 4) & 1)*8;
                int k = c*16 + ((lane >> 3) & 1)*8;
                uint32_t r4[4], b0[2], b1[2];
                ldsm_x4(Kbuf + (uint32_t)(n*AT_ROW + k)*2, r4);
                b0[0]=r4[0]; b0[1]=r4[1]; b1[0]=r4[2]; b1[1]=r4[3];
                mma_bf16(S0, qf[c], b0);
                mma_bf16(S1, qf[c], b1);
            }

            // ---- u = expm1(s) (mask pre-folded into K) ----
            float u00 = expm1_poly(S0[0]), u01 = expm1_poly(S0[1]);
            float u02 = expm1_poly(S0[2]), u03 = expm1_poly(S0[3]);
            float u10 = expm1_poly(S1[0]), u11 = expm1_poly(S1[1]);
            float u12 = expm1_poly(S1[2]), u13 = expm1_poly(S1[3]);
            l0 += u00 + u01 + u10 + u11;
            l1 += u02 + u03 + u12 + u13;

            uint32_t ua[4];
            ua[0] = pack_bf16x2(u00, u01);
            ua[1] = pack_bf16x2(u02, u03);
            ua[2] = pack_bf16x2(u10, u11);
            ua[3] = pack_bf16x2(u12, u13);

            // ---- O += U @ V (trans-ldmatrix B fragments) ----
#pragma unroll
            for (int np = 0; np < 4; np++) {
                int rs = p*16 + (lane & 7) + ((lane >> 3) & 1)*8;   // key (k)
                int cd = np*16 + ((lane >> 4) & 1)*8;               // dim (n)
                uint32_t r4[4], b0[2], b1[2];
                ldsm_x4_t(Vbuf + (uint32_t)(rs*AT_ROW + cd)*2, r4);
                b0[0]=r4[0]; b0[1]=r4[1]; b1[0]=r4[2]; b1[1]=r4[3];
                mma_bf16(O[2*np],   ua, b0);
                mma_bf16(O[2*np+1], ua, b1);
            }
        }
    }

    // ---- finalize ----
#pragma unroll
    for (int off = 1; off <= 2; off <<= 1) {
        l0 += __shfl_xor_sync(0xffffffffu, l0, off);
        l1 += __shfl_xor_sync(0xffffffffu, l1, off);
    }
    float msum = Msum[b];
    float inv0 = 1.f / (msum + l0), inv1 = 1.f / (msum + l1);

    int r0 = q0 + wid*16 + (lane >> 2);
    int r1 = r0 + 8;
#pragma unroll
    for (int nt = 0; nt < 8; nt++) {
        int dcol = nt*8 + (lane & 3)*2;
        float2 mv = *(const float2*)(Mv + b*EDIM + h*DD + dcol);
        float v0 = (O[nt][0] + mv.x) * inv0;
        float v1 = (O[nt][1] + mv.y) * inv0;
        float v2 = (O[nt][2] + mv.x) * inv1;
        float v3 = (O[nt][3] + mv.y) * inv1;
        size_t o0 = (size_t)(b*SS + r0)*EDIM + h*DD + dcol;
        size_t o1 = (size_t)(b*SS + r1)*EDIM + h*DD + dcol;
        uint32_t h0 = pack_bf16x2(v0, v1), h1 = pack_bf16x2(v2, v3);
        *(uint32_t*)(Ch + o0) = h0;
        *(uint32_t*)(Ch + o1) = h1;
        float f0 = __uint_as_float(h0 << 16);
        float f1 = __uint_as_float(h0 & 0xffff0000u);
        float f2 = __uint_as_float(h1 << 16);
        float f3 = __uint_as_float(h1 & 0xffff0000u);
        *(uint32_t*)(Cl + o0) = pack_bf16x2(v0 - f0, v1 - f1);
        *(uint32_t*)(Cl + o1) = pack_bf16x2(v2 - f2, v3 - f3);
    }
}

// ---------------- launch ----------------------------------------------------
extern "C" void kernel_launch(void* const* d_in, const int* in_sizes, int n_in,
                              void* d_out, int out_size)
{
    const float* q        = (const float*)d_in[0];
    const float* k        = (const float*)d_in[1];
    const float* v        = (const float*)d_in[2];
    const float* Wq       = (const float*)d_in[3];
    const float* bq       = (const float*)d_in[4];
    const float* Wk       = (const float*)d_in[5];
    const float* bk       = (const float*)d_in[6];
    const float* Wv_share = (const float*)d_in[7];
    const float* Wv_spec  = (const float*)d_in[8];
    const float* bv_share = (const float*)d_in[9];
    const float* bv_spec  = (const float*)d_in[10];
    const float* Wo_share = (const float*)d_in[11];
    const float* Wo_spec  = (const float*)d_in[12];
    const float* bo_share = (const float*)d_in[13];
    const float* bo_spec  = (const float*)d_in[14];
    const int*   mask     = (const int*)d_in[15];
    const int*   langp    = (const int*)d_in[16];
    float*       out      = (float*)d_out;

    bf16 *pqh,*pkh,*pvh,*pvl;
    bf16 *pWqh,*pWkh,*pWvh,*pWvl,*pWoh,*pWol;
    bf16 *pQh,*pKh,*pVh,*pVl,*pCh,*pCl;
    float *pbv,*pbo,*pMv,*pMs;
    cudaGetSymbolAddress((void**)&pqh, g_qh);
    cudaGetSymbolAddress((void**)&pkh, g_kh);
    cudaGetSymbolAddress((void**)&pvh, g_vh);  cudaGetSymbolAddress((void**)&pvl, g_vl);
    cudaGetSymbolAddress((void**)&pWqh, g_Wqh);
    cudaGetSymbolAddress((void**)&pWkh, g_Wkh);
    cudaGetSymbolAddress((void**)&pWvh, g_Wvh); cudaGetSymbolAddress((void**)&pWvl, g_Wvl);
    cudaGetSymbolAddress((void**)&pWoh, g_Woh); cudaGetSymbolAddress((void**)&pWol, g_Wol);
    cudaGetSymbolAddress((void**)&pQh, g_Qh);  cudaGetSymbolAddress((void**)&pKh, g_Kh);
    cudaGetSymbolAddress((void**)&pVh, g_Vh);  cudaGetSymbolAddress((void**)&pVl, g_Vl);
    cudaGetSymbolAddress((void**)&pCh, g_Ch);  cudaGetSymbolAddress((void**)&pCl, g_Cl);
    cudaGetSymbolAddress((void**)&pbv, g_bv);  cudaGetSymbolAddress((void**)&pbo, g_bo);
    cudaGetSymbolAddress((void**)&pMv, g_Mv);  cudaGetSymbolAddress((void**)&pMs, g_Msum);

    const int DS3 = 3*4*GS_ARRB;   // 122880
    const int DS1 = 3*2*GS_ARRB;   // 61440
    cudaFuncSetAttribute(attn_mma,
                         cudaFuncAttributeMaxDynamicSharedMemorySize, ATTN_SMEM);
    cudaFuncSetAttribute(gemm_mma<0,3,1>,
                         cudaFuncAttributeMaxDynamicSharedMemorySize, DS3);
    cudaFuncSetAttribute(gemm_mma<2,3,1>,
                         cudaFuncAttributeMaxDynamicSharedMemorySize, DS3);
    cudaFuncSetAttribute(gemm_mma<1,1,2>,
                         cudaFuncAttributeMaxDynamicSharedMemorySize, DS1);

    // 1. merged input splits + weight fuse/split
    split3_kernel<<<24576, 256>>>(q, k, v);
    fuse_weights_kernel<<<1024, 256>>>(Wq, Wk, Wv_share, Wv_spec, bv_share,
                                       bv_spec, Wo_share, Wo_spec, bo_share,
                                       bo_spec, langp);

    // 2. projections (Q folds the double 1/sqrt(D) = 1/64; K zeroes masked rows)
    dim3 gg(EDIM/128, MTOT/128);   // (4, 128)
    gemm_mma<1,1,2><<<gg, 256, DS1>>>(pqh, nullptr, pWqh, nullptr, bq, 1.0f/64.0f,
                                      nullptr, pQh, nullptr, nullptr);
    gemm_mma<1,1,2><<<gg, 256, DS1>>>(pkh, nullptr, pWkh, nullptr, bk, 1.0f,
                                      nullptr, pKh, nullptr, mask);
    gemm_mma<2,3,1><<<gg, 256, DS3>>>(pvh, pvl, pWvh, pWvl, pbv, 1.0f,
                                      nullptr, pVh, pVl, nullptr);

    // 2b. masked column sums of V
    dim3 gm1(8, BB);
    mv1_kernel<<<gm1, 512>>>(mask);
    mv2_kernel<<<BB, 512>>>();

    // 3. attention -> C (bf16 hi/lo)
    dim3 ga(SS/128, HH, BB);
    attn_mma<<<ga, 256, ATTN_SMEM>>>(pQh, pKh, pVh, pMv, pMs, pCh, pCl);

    // 4. output projection -> d_out (fp32)
    gemm_mma<0,3,1><<<gg, 256, DS3>>>(pCh, pCl, pWoh, pWol, pbo, 1.0f,
                                      out, nullptr, nullptr, nullptr);
}

// round 14
// speedup vs baseline: 1.9731x; 1.3968x over previous
#include <cuda_runtime.h>
#include <cuda_bf16.h>
#include <cstdint>

// Problem dims
#define EDIM 512
#define BB   16
#define SS   1024
#define HH   8
#define DD   64
#define MTOT (BB*SS)   // 16384
#define LL   4

typedef __nv_bfloat16 bf16;

// ---------------- scratch (device globals; no allocation allowed) ----------
__device__ bf16 g_qh[(size_t)MTOT*EDIM];
__device__ bf16 g_kh[(size_t)MTOT*EDIM];
__device__ bf16 g_vh[(size_t)MTOT*EDIM];
__device__ bf16 g_Wqh[EDIM*EDIM];
__device__ bf16 g_Wkh[EDIM*EDIM];
__device__ bf16 g_Wvh[EDIM*EDIM], g_Wvl[EDIM*EDIM];
__device__ bf16 g_Woh[EDIM*EDIM], g_Wol[EDIM*EDIM];
__device__ float g_bv[EDIM], g_bo[EDIM];
__device__ bf16 g_Qh[(size_t)MTOT*EDIM];           // projected Q (hi only)
__device__ bf16 g_Kh[(size_t)MTOT*EDIM];           // projected K (hi, masked rows zeroed)
__device__ bf16 g_Vh[(size_t)MTOT*EDIM];           // projected V (hi only)
__device__ bf16 g_Ch[(size_t)MTOT*EDIM];           // UV * invl (residual, bf16)
__device__ float g_vsPart[BB*8*EDIM];              // partial masked col sums of input v
__device__ float g_MsPart[BB*8];
__device__ float g_vsum[BB*EDIM];
__device__ float g_Mv[BB*EDIM];
__device__ float g_Msum[BB];
__device__ float g_MW[(size_t)BB*EDIM*8];          // MW[b][n][h]
__device__ float g_invl[(size_t)BB*SS*8];          // invl[b][s][h]

// ======================= helpers ===========================================
__device__ __forceinline__ uint32_t smem_u32(const void* p) {
    uint32_t a;
    asm("{ .reg .u64 t; cvta.to.shared.u64 t, %1; cvt.u32.u64 %0, t; }"
        : "=r"(a) : "l"(p));
    return a;
}

__device__ __forceinline__ void ldsm_x4(uint32_t addr, uint32_t r[4]) {
    asm volatile("ldmatrix.sync.aligned.m8n8.x4.shared.b16 {%0,%1,%2,%3}, [%4];"
        : "=r"(r[0]), "=r"(r[1]), "=r"(r[2]), "=r"(r[3]) : "r"(addr));
}

__device__ __forceinline__ void ldsm_x4_t(uint32_t addr, uint32_t r[4]) {
    asm volatile("ldmatrix.sync.aligned.m8n8.x4.trans.shared.b16 {%0,%1,%2,%3}, [%4];"
        : "=r"(r[0]), "=r"(r[1]), "=r"(r[2]), "=r"(r[3]) : "r"(addr));
}

__device__ __forceinline__ void mma_bf16(float d[4], const uint32_t a[4],
                                         const uint32_t b[2]) {
    asm volatile(
        "mma.sync.aligned.m16n8k16.row.col.f32.bf16.bf16.f32 "
        "{%0,%1,%2,%3}, {%4,%5,%6,%7}, {%8,%9}, {%0,%1,%2,%3};"
        : "+f"(d[0]), "+f"(d[1]), "+f"(d[2]), "+f"(d[3])
        : "r"(a[0]), "r"(a[1]), "r"(a[2]), "r"(a[3]), "r"(b[0]), "r"(b[1]));
}

__device__ __forceinline__ uint32_t pack_bf16x2(float lo, float hi) {
    uint32_t r;
    asm("cvt.rn.bf16x2.f32 %0, %1, %2;" : "=r"(r) : "f"(hi), "f"(lo));
    return r;
}

__device__ __forceinline__ void split1(float x, bf16& h, bf16& l) {
    h = __float2bfloat16_rn(x);
    l = __float2bfloat16_rn(x - __bfloat162float(h));
}

__device__ __forceinline__ uint2 pack_hi4(const float4 v) {
    uint2 h;
    h.x = pack_bf16x2(v.x, v.y);
    h.y = pack_bf16x2(v.z, v.w);
    return h;
}

// expm1(x) for |x| <~ 0.5
__device__ __forceinline__ float expm1_poly(float x) {
    float c = 8.33333333e-3f;
    c = fmaf(c, x, 4.16666667e-2f);
    c = fmaf(c, x, 1.66666667e-1f);
    c = fmaf(c, x, 0.5f);
    c = fmaf(c, x, 1.0f);
    return x * c;
}

__device__ __forceinline__ void cp16(uint32_t dst, const void* src) {
    asm volatile("cp.async.cg.shared.global [%0], [%1], 16;"
                 :: "r"(dst), "l"(src) : "memory");
}
__device__ __forceinline__ void cp_commit() {
    asm volatile("cp.async.commit_group;" ::: "memory");
}
__device__ __forceinline__ void cp_wait0() {
    asm volatile("cp.async.wait_group 0;" ::: "memory");
}
__device__ __forceinline__ void cp_wait1() {
    asm volatile("cp.async.wait_group 1;" ::: "memory");
}

// ---------------- merged input splits (hi only, uniform blocks) ------------
__global__ __launch_bounds__(256) void split3_kernel(
    const float* __restrict__ q, const float* __restrict__ k,
    const float* __restrict__ v)
{
    const int blk = blockIdx.x;
    const int which = blk >> 13;
    size_t i = ((size_t)(blk & 8191))*256 + threadIdx.x;
    const float* src = (which == 0) ? q : (which == 1) ? k : v;
    float4 val = *(const float4*)(src + i*4);
    uint2 h = pack_hi4(val);
    if (which == 0)      *(uint2*)(g_qh + i*4) = h;
    else if (which == 1) *(uint2*)(g_kh + i*4) = h;
    else                 *(uint2*)(g_vh + i*4) = h;
}

// ---------------- weight fusion + split ------------------------------------
__global__ __launch_bounds__(256) void fuse_weights_kernel(
    const float* __restrict__ Wq, const float* __restrict__ Wk,
    const float* __restrict__ Wvs, const float* __restrict__ Wvp,
    const float* __restrict__ bvs, const float* __restrict__ bvp,
    const float* __restrict__ Wos, const float* __restrict__ Wop,
    const float* __restrict__ bos, const float* __restrict__ bop,
    const int*  __restrict__ langp)
{
    int lang = langp[0];
    if (lang < 0 || lang >= LL) {
        float f = __int_as_float(lang);
        int li = (int)f;
        lang = (li >= 0 && li < LL) ? li : 0;
    }
    int i = blockIdx.x * blockDim.x + threadIdx.x;
    if (i < EDIM*EDIM) {
        size_t off = (size_t)lang * EDIM * EDIM + i;
        g_Wqh[i] = __float2bfloat16_rn(Wq[i]);
        g_Wkh[i] = __float2bfloat16_rn(Wk[i]);
        split1(Wvs[i] * Wvp[off], g_Wvh[i], g_Wvl[i]);
        split1(Wos[i] * Wop[off], g_Woh[i], g_Wol[i]);
    }
    if (i < EDIM) {
        g_bv[i] = bvs[i] + bvp[lang*EDIM + i];
        g_bo[i] = bos[i] + bop[lang*EDIM + i];
    }
}

// ---------------- masked column sums of INPUT v (2-phase) ------------------
__global__ __launch_bounds__(512) void vsum1_kernel(
    const float* __restrict__ v, const int* __restrict__ mask)
{
    const int sc = blockIdx.x, b = blockIdx.y, e = threadIdx.x;
    float acc = 0.f;
    const int s0 = b*SS + sc*128;
#pragma unroll 4
    for (int s = 0; s < 128; s++)
        if (mask[s0 + s] != 0)
            acc += v[(size_t)(s0 + s)*EDIM + e];
    g_vsPart[(b*8 + sc)*EDIM + e] = acc;
    if (e == 0) {
        int c = 0;
        for (int s = 0; s < 128; s++) c += (mask[s0 + s] != 0);
        g_MsPart[b*8 + sc] = (float)c;
    }
}

__global__ __launch_bounds__(512) void vsum2_kernel()
{
    const int b = blockIdx.x, e = threadIdx.x;
    float acc = 0.f;
#pragma unroll
    for (int sc = 0; sc < 8; sc++) acc += g_vsPart[(b*8 + sc)*EDIM + e];
    g_vsum[b*EDIM + e] = acc;
    if (e == 0) {
        float c = 0.f;
#pragma unroll
        for (int sc = 0; sc < 8; sc++) c += g_MsPart[b*8 + sc];
        g_Msum[b] = c;
    }
}

// ---------------- Mv[b][n] = vsum[b] . Wv[n] + cnt*bv[n] (warp per out) ----
__global__ __launch_bounds__(256) void mv_gemm_kernel()
{
    const int w = blockIdx.x*8 + (threadIdx.x >> 5);   // 8192 warps
    const int lane = threadIdx.x & 31;
    const int b = w >> 9, n = w & 511;
    float acc = 0.f;
#pragma unroll
    for (int t = 0; t < 16; t++) {
        int e = t*32 + lane;
        float wv = __bfloat162float(g_Wvh[(size_t)n*EDIM + e])
                 + __bfloat162float(g_Wvl[(size_t)n*EDIM + e]);
        acc = fmaf(g_vsum[b*EDIM + e], wv, acc);
    }
#pragma unroll
    for (int o = 16; o; o >>= 1) acc += __shfl_xor_sync(0xffffffffu, acc, o);
    if (lane == 0)
        g_Mv[b*EDIM + n] = acc + g_Msum[b]*g_bv[n];
}

// ---------------- MW[b][n][h] = sum_{e in head h} Mv[b][e]*Wo[n][e] --------
__global__ __launch_bounds__(256) void mw_kernel()
{
    const int w = blockIdx.x*8 + (threadIdx.x >> 5);   // 8192 warps
    const int lane = threadIdx.x & 31;
    const int b = w >> 9, n = w & 511;
    float ph[8];
#pragma unroll
    for (int h = 0; h < 8; h++) ph[h] = 0.f;
#pragma unroll
    for (int t = 0; t < 16; t++) {
        int e = t*32 + lane;
        float wo = __bfloat162float(g_Woh[(size_t)n*EDIM + e])
                 + __bfloat162float(g_Wol[(size_t)n*EDIM + e]);
        ph[t >> 1] = fmaf(g_Mv[b*EDIM + e], wo, ph[t >> 1]);
    }
#pragma unroll
    for (int h = 0; h < 8; h++)
#pragma unroll
        for (int o = 16; o; o >>= 1)
            ph[h] += __shfl_xor_sync(0xffffffffu, ph[h], o);
    if (lane == 0) {
        float* dst = g_MW + ((size_t)b*EDIM + n)*8;
#pragma unroll
        for (int h = 0; h < 8; h++) dst[h] = ph[h];
    }
}

// =================== cp.async bf16 GEMM ====================================
// MODE 1: bf16 hi out. MODE 3: fp32 out with Mv-path epilogue
//   out = acc + sum_h invl[b,s,h]*MW[b,col,h] + bias[col]
// NPROD 3: hi/lo operands, 3-product. NPROD 1: hi-only, 1 product.
#define GS_ROW   40
#define GS_ARRB  10240                     // bytes per array per stage (128*40*2)

template<int MODE, int NPROD, int MINB>
__global__ __launch_bounds__(256, MINB) void gemm_mma(
    const bf16* __restrict__ Ahi, const bf16* __restrict__ Alo,
    const bf16* __restrict__ Bhi, const bf16* __restrict__ Blo,
    const float* __restrict__ bias, float scale,
    float* __restrict__ outF, bf16* __restrict__ outHi,
    const int* __restrict__ maskp,
    const float* __restrict__ mwp, const float* __restrict__ invlp)
{
    extern __shared__ __align__(128) bf16 smem[];
    constexpr int NARR = (NPROD == 3) ? 4 : 2;
    constexpr uint32_t STAGEB = NARR * GS_ARRB;

    const int tid  = threadIdx.x;
    const int lane = tid & 31;
    const int wid  = tid >> 5;
    const int wm   = wid >> 1;
    const int wn   = wid & 1;
    const int m0   = blockIdx.y * 128;
    const int n0   = blockIdx.x * 128;

    const uint32_t sb = smem_u32(smem);

    auto cp_stage = [&](int ks, int buf) {
        uint32_t sbase = sb + (uint32_t)buf * STAGEB;
#pragma unroll
        for (int c8 = 0; c8 < NARR*2; c8++) {
            int j = c8*256 + tid;
            int arr = j >> 9, jj = j & 511;
            int row = jj >> 2, cc = jj & 3;
            const bf16* src;
            if (NPROD == 3) {
                if      (arr == 0) src = Ahi + (size_t)(m0+row)*EDIM + ks*32 + cc*8;
                else if (arr == 1) src = Alo + (size_t)(m0+row)*EDIM + ks*32 + cc*8;
                else if (arr == 2) src = Bhi + (size_t)(n0+row)*EDIM + ks*32 + cc*8;
                else               src = Blo + (size_t)(n0+row)*EDIM + ks*32 + cc*8;
            } else {
                src = (arr == 0) ? Ahi + (size_t)(m0+row)*EDIM + ks*32 + cc*8
                                 : Bhi + (size_t)(n0+row)*EDIM + ks*32 + cc*8;
            }
            uint32_t dst = sbase + (uint32_t)arr*GS_ARRB + (uint32_t)(row*GS_ROW + cc*8)*2;
            cp16(dst, src);
        }
        cp_commit();
    };

    float d[2][8][4];
#pragma unroll
    for (int mt = 0; mt < 2; mt++)
#pragma unroll
        for (int nt = 0; nt < 8; nt++)
#pragma unroll
            for (int u = 0; u < 4; u++) d[mt][nt][u] = 0.f;

    cp_stage(0, 0);
    cp_stage(1, 1);

    for (int ks = 0; ks < 16; ks++) {
        if (ks < 15) cp_wait1(); else cp_wait0();
        __syncthreads();
        if (ks + 2 < 16) cp_stage(ks + 2, (ks + 2) % 3);

        const uint32_t base = sb + (uint32_t)(ks % 3) * STAGEB;
        const uint32_t aHi = base;
        const uint32_t aLo = base + GS_ARRB;
        const uint32_t bHi = base + (NPROD == 3 ? 2 : 1)*GS_ARRB;
        const uint32_t bLo = base + 3*GS_ARRB;

#pragma unroll
        for (int kk = 0; kk < 2; kk++) {
            const int kc = kk * 16;
            uint32_t ah[2][4], al[2][4];
            {
                int r = wm*32 + (lane & 7) + ((lane >> 3) & 1)*8;
                int k = kc + ((lane >> 4) & 1)*8;
                uint32_t off = (uint32_t)(r*GS_ROW + k)*2;
#pragma unroll
                for (int mt = 0; mt < 2; mt++) {
                    ldsm_x4(aHi + off + (uint32_t)(mt*16*GS_ROW)*2, ah[mt]);
                    if (NPROD == 3)
                        ldsm_x4(aLo + off + (uint32_t)(mt*16*GS_ROW)*2, al[mt]);
                }
            }
            uint32_t bh[8][2], bl[8][2];
            {
                int n = wn*64 + (lane & 7) + ((lane >> 4) & 1)*8;
                int k = kc + ((lane >> 3) & 1)*8;
                uint32_t off = (uint32_t)(n*GS_ROW + k)*2;
#pragma unroll
                for (int q = 0; q < 4; q++) {
                    uint32_t r4[4];
                    ldsm_x4(bHi + off + (uint32_t)(q*16*GS_ROW)*2, r4);
                    bh[2*q][0] = r4[0]; bh[2*q][1] = r4[1];
                    bh[2*q+1][0] = r4[2]; bh[2*q+1][1] = r4[3];
                    if (NPROD == 3) {
                        ldsm_x4(bLo + off + (uint32_t)(q*16*GS_ROW)*2, r4);
                        bl[2*q][0] = r4[0]; bl[2*q][1] = r4[1];
                        bl[2*q+1][0] = r4[2]; bl[2*q+1][1] = r4[3];
                    }
                }
            }
#pragma unroll
            for (int mt = 0; mt < 2; mt++)
#pragma unroll
                for (int nt = 0; nt < 8; nt++) {
                    mma_bf16(d[mt][nt], ah[mt], bh[nt]);
                    if (NPROD == 3) {
                        mma_bf16(d[mt][nt], ah[mt], bl[nt]);
                        mma_bf16(d[mt][nt], al[mt], bh[nt]);
                    }
                }
        }
    }

    // ---------------- epilogue --------------------------------------------
#pragma unroll
    for (int mt = 0; mt < 2; mt++) {
        int row0 = m0 + wm*32 + mt*16 + (lane >> 2);
        float mr0 = 1.f, mr1 = 1.f;
        if (maskp != nullptr) {
            mr0 = (maskp[row0] != 0) ? 1.f : 0.f;
            mr1 = (maskp[row0 + 8] != 0) ? 1.f : 0.f;
        }
        float iv0[8], iv1[8];
        if (MODE == 3) {
            const float* p0 = invlp + (size_t)row0*8;       // row0 = b*SS+s
            const float* p1 = p0 + 64;                       // row0+8
            float4 a0 = *(const float4*)p0, b0v = *(const float4*)(p0+4);
            float4 a1 = *(const float4*)p1, b1v = *(const float4*)(p1+4);
            iv0[0]=a0.x; iv0[1]=a0.y; iv0[2]=a0.z; iv0[3]=a0.w;
            iv0[4]=b0v.x; iv0[5]=b0v.y; iv0[6]=b0v.z; iv0[7]=b0v.w;
            iv1[0]=a1.x; iv1[1]=a1.y; iv1[2]=a1.z; iv1[3]=a1.w;
            iv1[4]=b1v.x; iv1[5]=b1v.y; iv1[6]=b1v.z; iv1[7]=b1v.w;
        }
#pragma unroll
        for (int nt = 0; nt < 8; nt++) {
            int col = n0 + wn*64 + nt*8 + (lane & 3)*2;
            float b0 = bias[col], b1 = bias[col + 1];
            size_t o0 = (size_t)row0*EDIM + col;
            size_t o1 = (size_t)(row0 + 8)*EDIM + col;
            if (MODE == 3) {
                const int bb = row0 >> 10;
                const float* mw0 = mwp + ((size_t)bb*EDIM + col)*8;
                const float* mw1 = mw0 + 8;
                float dotA0 = 0.f, dotA1 = 0.f, dotB0 = 0.f, dotB1 = 0.f;
#pragma unroll
                for (int h = 0; h < 8; h++) {
                    float m0v = mw0[h], m1v = mw1[h];
                    dotA0 = fmaf(iv0[h], m0v, dotA0);
                    dotA1 = fmaf(iv0[h], m1v, dotA1);
                    dotB0 = fmaf(iv1[h], m0v, dotB0);
                    dotB1 = fmaf(iv1[h], m1v, dotB1);
                }
                *(float2*)(outF + o0) = make_float2(d[mt][nt][0] + dotA0 + b0,
                                                    d[mt][nt][1] + dotA1 + b1);
                *(float2*)(outF + o1) = make_float2(d[mt][nt][2] + dotB0 + b0,
                                                    d[mt][nt][3] + dotB1 + b1);
            } else {
                float v0 = (d[mt][nt][0] + b0) * scale * mr0;
                float v1 = (d[mt][nt][1] + b1) * scale * mr0;
                float v2 = (d[mt][nt][2] + b0) * scale * mr1;
                float v3 = (d[mt][nt][3] + b1) * scale * mr1;
                *(uint32_t*)(outHi + o0) = pack_bf16x2(v0, v1);
                *(uint32_t*)(outHi + o1) = pack_bf16x2(v2, v3);
            }
        }
    }
}

// =================== attention: residual-only output ========================
// Writes Ch = (U@V)*invl (bf16) and invl[b][s][h]. Mv handled downstream.
#define AT_ROW   72
#define AT_QOFF  0
#define AT_KV(buf)   (18432 + (buf)*36864)
#define AT_VOFF(buf) (AT_KV(buf) + 18432)
#define ATTN_SMEM 92160

__global__ __launch_bounds__(256, 2) void attn_mma(
    const bf16* __restrict__ Qh, const bf16* __restrict__ Kh,
    const bf16* __restrict__ Vh, const float* __restrict__ Msum,
    bf16* __restrict__ Ch, float* __restrict__ invlp)
{
    extern __shared__ __align__(128) bf16 sm[];

    const int tid  = threadIdx.x;
    const int lane = tid & 31;
    const int wid  = tid >> 5;
    const int b    = blockIdx.z, h = blockIdx.y;
    const int q0   = blockIdx.x * 128;

    const uint32_t sb = smem_u32(sm);

    auto cp_kv = [&](int kb, int buf) {
#pragma unroll
        for (int c8 = 0; c8 < 8; c8++) {
            int j = c8*256 + tid;
            int arr = j >> 10, jj = j & 1023;
            int row = jj >> 3, cc = jj & 7;
            const bf16* src = (arr ? Vh : Kh)
                + (size_t)(b*SS + kb*128 + row)*EDIM + h*DD + cc*8;
            uint32_t dst = sb + (arr ? AT_VOFF(buf) : AT_KV(buf))
                + (uint32_t)(row*AT_ROW + cc*8)*2;
            cp16(dst, src);
        }
        cp_commit();
    };

    // ---- Q tile (plain loads) ----
#pragma unroll
    for (int c4 = 0; c4 < 4; c4++) {
        int j = c4*256 + tid;
        int row = j >> 3, cc = j & 7;
        uint4 v = *(const uint4*)(Qh + (size_t)(b*SS + q0 + row)*EDIM + h*DD + cc*8);
        uint32_t dst = sb + AT_QOFF + (uint32_t)(row*AT_ROW + cc*8)*2;
        asm volatile("st.shared.v4.b32 [%0], {%1,%2,%3,%4};"
                     :: "r"(dst), "r"(v.x), "r"(v.y), "r"(v.z), "r"(v.w));
    }
    cp_kv(0, 0);
    __syncthreads();

    // ---- Q fragments (single bf16) ----
    uint32_t qf[4][4];
    {
        int r = wid*16 + (lane & 7) + ((lane >> 3) & 1)*8;
#pragma unroll
        for (int kc = 0; kc < 4; kc++) {
            int k = kc*16 + ((lane >> 4) & 1)*8;
            ldsm_x4(sb + AT_QOFF + (uint32_t)(r*AT_ROW + k)*2, qf[kc]);
        }
    }

    float l0 = 0.f, l1 = 0.f;
    float O[8][4];
#pragma unroll
    for (int nt = 0; nt < 8; nt++)
#pragma unroll
        for (int u = 0; u < 4; u++) O[nt][u] = 0.f;

    for (int kb = 0; kb < SS/128; kb++) {
        cp_wait0();
        __syncthreads();
        if (kb + 1 < SS/128) cp_kv(kb + 1, (kb + 1) & 1);
        const uint32_t Kbuf = sb + AT_KV(kb & 1);
        const uint32_t Vbuf = sb + AT_VOFF(kb & 1);

#pragma unroll
        for (int p = 0; p < 8; p++) {
            float S0[4] = {0.f, 0.f, 0.f, 0.f};
            float S1[4] = {0.f, 0.f, 0.f, 0.f};
#pragma unroll
            for (int c = 0; c < 4; c++) {
                int n = 16*p + (lane & 7) + ((lane >> 4) & 1)*8;
                int k = c*16 + ((lane >> 3) & 1)*8;
                uint32_t r4[4], b0[2], b1[2];
                ldsm_x4(Kbuf + (uint32_t)(n*AT_ROW + k)*2, r4);
                b0[0]=r4[0]; b0[1]=r4[1]; b1[0]=r4[2]; b1[1]=r4[3];
                mma_bf16(S0, qf[c], b0);
                mma_bf16(S1, qf[c], b1);
            }

            float u00 = expm1_poly(S0[0]), u01 = expm1_poly(S0[1]);
            float u02 = expm1_poly(S0[2]), u03 = expm1_poly(S0[3]);
            float u10 = expm1_poly(S1[0]), u11 = expm1_poly(S1[1]);
            float u12 = expm1_poly(S1[2]), u13 = expm1_poly(S1[3]);
            l0 += u00 + u01 + u10 + u11;
            l1 += u02 + u03 + u12 + u13;

            uint32_t ua[4];
            ua[0] = pack_bf16x2(u00, u01);
            ua[1] = pack_bf16x2(u02, u03);
            ua[2] = pack_bf16x2(u10, u11);
            ua[3] = pack_bf16x2(u12, u13);

#pragma unroll
            for (int np = 0; np < 4; np++) {
                int rs = p*16 + (lane & 7) + ((lane >> 3) & 1)*8;
                int cd = np*16 + ((lane >> 4) & 1)*8;
                uint32_t r4[4], b0[2], b1[2];
                ldsm_x4_t(Vbuf + (uint32_t)(rs*AT_ROW + cd)*2, r4);
                b0[0]=r4[0]; b0[1]=r4[1]; b1[0]=r4[2]; b1[1]=r4[3];
                mma_bf16(O[2*np],   ua, b0);
                mma_bf16(O[2*np+1], ua, b1);
            }
        }
    }

    // ---- finalize: residual only ----
#pragma unroll
    for (int off = 1; off <= 2; off <<= 1) {
        l0 += __shfl_xor_sync(0xffffffffu, l0, off);
        l1 += __shfl_xor_sync(0xffffffffu, l1, off);
    }
    float msum = Msum[b];
    float inv0 = 1.f / (msum + l0), inv1 = 1.f / (msum + l1);

    int r0 = q0 + wid*16 + (lane >> 2);   // s within batch
    int r1 = r0 + 8;
    if ((lane & 3) == 0) {
        invlp[((size_t)b*SS + r0)*8 + h] = inv0;
        invlp[((size_t)b*SS + r1)*8 + h] = inv1;
    }
#pragma unroll
    for (int nt = 0; nt < 8; nt++) {
        int dcol = nt*8 + (lane & 3)*2;
        size_t o0 = (size_t)(b*SS + r0)*EDIM + h*DD + dcol;
        size_t o1 = (size_t)(b*SS + r1)*EDIM + h*DD + dcol;
        *(uint32_t*)(Ch + o0) = pack_bf16x2(O[nt][0]*inv0, O[nt][1]*inv0);
        *(uint32_t*)(Ch + o1) = pack_bf16x2(O[nt][2]*inv1, O[nt][3]*inv1);
    }
}

// ---------------- launch ----------------------------------------------------
extern "C" void kernel_launch(void* const* d_in, const int* in_sizes, int n_in,
                              void* d_out, int out_size)
{
    const float* q        = (const float*)d_in[0];
    const float* k        = (const float*)d_in[1];
    const float* v        = (const float*)d_in[2];
    const float* Wq       = (const float*)d_in[3];
    const float* bq       = (const float*)d_in[4];
    const float* Wk       = (const float*)d_in[5];
    const float* bk       = (const float*)d_in[6];
    const float* Wv_share = (const float*)d_in[7];
    const float* Wv_spec  = (const float*)d_in[8];
    const float* bv_share = (const float*)d_in[9];
    const float* bv_spec  = (const float*)d_in[10];
    const float* Wo_share = (const float*)d_in[11];
    const float* Wo_spec  = (const float*)d_in[12];
    const float* bo_share = (const float*)d_in[13];
    const float* bo_spec  = (const float*)d_in[14];
    const int*   mask     = (const int*)d_in[15];
    const int*   langp    = (const int*)d_in[16];
    float*       out      = (float*)d_out;

    bf16 *pqh,*pkh,*pvh;
    bf16 *pWqh,*pWkh,*pWvh,*pWoh;
    bf16 *pQh,*pKh,*pVh,*pCh;
    float *pbo,*pMs,*pMW,*pInvl;
    cudaGetSymbolAddress((void**)&pqh, g_qh);
    cudaGetSymbolAddress((void**)&pkh, g_kh);
    cudaGetSymbolAddress((void**)&pvh, g_vh);
    cudaGetSymbolAddress((void**)&pWqh, g_Wqh);
    cudaGetSymbolAddress((void**)&pWkh, g_Wkh);
    cudaGetSymbolAddress((void**)&pWvh, g_Wvh);
    cudaGetSymbolAddress((void**)&pWoh, g_Woh);
    cudaGetSymbolAddress((void**)&pQh, g_Qh);  cudaGetSymbolAddress((void**)&pKh, g_Kh);
    cudaGetSymbolAddress((void**)&pVh, g_Vh);  cudaGetSymbolAddress((void**)&pCh, g_Ch);
    cudaGetSymbolAddress((void**)&pbo, g_bo);
    cudaGetSymbolAddress((void**)&pMs, g_Msum);
    cudaGetSymbolAddress((void**)&pMW, g_MW);
    cudaGetSymbolAddress((void**)&pInvl, g_invl);
    float* pbq_dummy = nullptr; (void)pbq_dummy;

    const int DS1 = 3*2*GS_ARRB;   // 61440
    cudaFuncSetAttribute(attn_mma,
                         cudaFuncAttributeMaxDynamicSharedMemorySize, ATTN_SMEM);
    cudaFuncSetAttribute(gemm_mma<1,1,2>,
                         cudaFuncAttributeMaxDynamicSharedMemorySize, DS1);
    cudaFuncSetAttribute(gemm_mma<3,1,2>,
                         cudaFuncAttributeMaxDynamicSharedMemorySize, DS1);

    // 1. input splits + weight fuse/split
    split3_kernel<<<24576, 256>>>(q, k, v);
    fuse_weights_kernel<<<1024, 256>>>(Wq, Wk, Wv_share, Wv_spec, bv_share,
                                       bv_spec, Wo_share, Wo_spec, bo_share,
                                       bo_spec, langp);

    // 2. masked column sums of input v + counts
    dim3 gv1(8, BB);
    vsum1_kernel<<<gv1, 512>>>(v, mask);
    vsum2_kernel<<<BB, 512>>>();

    // 3. projections (all 1-product; K zeroes masked rows)
    dim3 gg(EDIM/128, MTOT/128);   // (4, 128)
    gemm_mma<1,1,2><<<gg, 256, DS1>>>(pqh, nullptr, pWqh, nullptr, bq, 1.0f/64.0f,
                                      nullptr, pQh, nullptr, nullptr, nullptr);
    gemm_mma<1,1,2><<<gg, 256, DS1>>>(pkh, nullptr, pWkh, nullptr, bk, 1.0f,
                                      nullptr, pKh, mask, nullptr, nullptr);
    {
        float* pbv_; cudaGetSymbolAddress((void**)&pbv_, g_bv);
        gemm_mma<1,1,2><<<gg, 256, DS1>>>(pvh, nullptr, pWvh, nullptr, pbv_, 1.0f,
                                          nullptr, pVh, nullptr, nullptr, nullptr);
    }

    // 4. Mv (fp32 analytic) and MW precompute
    mv_gemm_kernel<<<1024, 256>>>();
    mw_kernel<<<1024, 256>>>();

    // 5. attention -> residual C (bf16) + invl
    dim3 ga(SS/128, HH, BB);
    attn_mma<<<ga, 256, ATTN_SMEM>>>(pQh, pKh, pVh, pMs, pCh, pInvl);

    // 6. output projection (residual) + Mv-path epilogue -> d_out (fp32)
    gemm_mma<3,1,2><<<gg, 256, DS1>>>(pCh, nullptr, pWoh, nullptr, pbo, 1.0f,
                                      out, nullptr, nullptr, pMW, pInvl);
}

// round 15
// speedup vs baseline: 2.0283x; 1.0279x over previous
#include <cuda_runtime.h>
#include <cuda_bf16.h>
#include <cstdint>

// Problem dims
#define EDIM 512
#define BB   16
#define SS   1024
#define HH   8
#define DD   64
#define MTOT (BB*SS)   // 16384
#define LL   4

typedef __nv_bfloat16 bf16;

// ---------------- scratch (device globals; no allocation allowed) ----------
__device__ bf16 g_in3[(size_t)3*MTOT*EDIM];        // split q,k,v (hi)
__device__ bf16 g_W3[(size_t)3*EDIM*EDIM];         // Wq,Wk,Wv (hi)
__device__ bf16 g_P3[(size_t)3*MTOT*EDIM];         // projected Q,K,V (hi)
__device__ float g_b3[3*EDIM];                     // bq, bk, bv(fused)
__device__ bf16 g_Wvl[EDIM*EDIM];
__device__ bf16 g_Woh[EDIM*EDIM], g_Wol[EDIM*EDIM];
__device__ float g_bo[EDIM];
__device__ bf16 g_Ch[(size_t)MTOT*EDIM];           // UV * invl (residual, bf16)
__device__ float g_vsPart[BB*8*EDIM];
__device__ float g_MsPart[BB*8];
__device__ float g_vsum[BB*EDIM];
__device__ float g_Mv[BB*EDIM];
__device__ float g_Msum[BB];
__device__ float g_MW[(size_t)BB*EDIM*8];          // MW[b][n][h]
__device__ float g_invl[(size_t)BB*SS*8];          // invl[b][s][h]

// ======================= helpers ===========================================
__device__ __forceinline__ uint32_t smem_u32(const void* p) {
    uint32_t a;
    asm("{ .reg .u64 t; cvta.to.shared.u64 t, %1; cvt.u32.u64 %0, t; }"
        : "=r"(a) : "l"(p));
    return a;
}

__device__ __forceinline__ void ldsm_x4(uint32_t addr, uint32_t r[4]) {
    asm volatile("ldmatrix.sync.aligned.m8n8.x4.shared.b16 {%0,%1,%2,%3}, [%4];"
        : "=r"(r[0]), "=r"(r[1]), "=r"(r[2]), "=r"(r[3]) : "r"(addr));
}

__device__ __forceinline__ void ldsm_x4_t(uint32_t addr, uint32_t r[4]) {
    asm volatile("ldmatrix.sync.aligned.m8n8.x4.trans.shared.b16 {%0,%1,%2,%3}, [%4];"
        : "=r"(r[0]), "=r"(r[1]), "=r"(r[2]), "=r"(r[3]) : "r"(addr));
}

__device__ __forceinline__ void mma_bf16(float d[4], const uint32_t a[4],
                                         const uint32_t b[2]) {
    asm volatile(
        "mma.sync.aligned.m16n8k16.row.col.f32.bf16.bf16.f32 "
        "{%0,%1,%2,%3}, {%4,%5,%6,%7}, {%8,%9}, {%0,%1,%2,%3};"
        : "+f"(d[0]), "+f"(d[1]), "+f"(d[2]), "+f"(d[3])
        : "r"(a[0]), "r"(a[1]), "r"(a[2]), "r"(a[3]), "r"(b[0]), "r"(b[1]));
}

__device__ __forceinline__ uint32_t pack_bf16x2(float lo, float hi) {
    uint32_t r;
    asm("cvt.rn.bf16x2.f32 %0, %1, %2;" : "=r"(r) : "f"(hi), "f"(lo));
    return r;
}

__device__ __forceinline__ void split1(float x, bf16& h, bf16& l) {
    h = __float2bfloat16_rn(x);
    l = __float2bfloat16_rn(x - __bfloat162float(h));
}

__device__ __forceinline__ uint2 pack_hi4(const float4 v) {
    uint2 h;
    h.x = pack_bf16x2(v.x, v.y);
    h.y = pack_bf16x2(v.z, v.w);
    return h;
}

// expm1(x) for |x| <~ 0.5
__device__ __forceinline__ float expm1_poly(float x) {
    float c = 8.33333333e-3f;
    c = fmaf(c, x, 4.16666667e-2f);
    c = fmaf(c, x, 1.66666667e-1f);
    c = fmaf(c, x, 0.5f);
    c = fmaf(c, x, 1.0f);
    return x * c;
}

__device__ __forceinline__ void cp16(uint32_t dst, const void* src) {
    asm volatile("cp.async.cg.shared.global [%0], [%1], 16;"
                 :: "r"(dst), "l"(src) : "memory");
}
__device__ __forceinline__ void cp_commit() {
    asm volatile("cp.async.commit_group;" ::: "memory");
}
__device__ __forceinline__ void cp_wait0() {
    asm volatile("cp.async.wait_group 0;" ::: "memory");
}
__device__ __forceinline__ void cp_wait1() {
    asm volatile("cp.async.wait_group 1;" ::: "memory");
}

// ---------------- merged input splits (hi only, uniform blocks) ------------
__global__ __launch_bounds__(256) void split3_kernel(
    const float* __restrict__ q, const float* __restrict__ k,
    const float* __restrict__ v)
{
    const int blk = blockIdx.x;
    const int which = blk >> 13;
    size_t i = ((size_t)(blk & 8191))*256 + threadIdx.x;
    const float* src = (which == 0) ? q : (which == 1) ? k : v;
    float4 val = *(const float4*)(src + i*4);
    *(uint2*)(g_in3 + (size_t)which*MTOT*EDIM + i*4) = pack_hi4(val);
}

// ---------------- weight fusion + split ------------------------------------
__global__ __launch_bounds__(256) void fuse_weights_kernel(
    const float* __restrict__ Wq, const float* __restrict__ Wk,
    const float* __restrict__ bq, const float* __restrict__ bk,
    const float* __restrict__ Wvs, const float* __restrict__ Wvp,
    const float* __restrict__ bvs, const float* __restrict__ bvp,
    const float* __restrict__ Wos, const float* __restrict__ Wop,
    const float* __restrict__ bos, const float* __restrict__ bop,
    const int*  __restrict__ langp)
{
    int lang = langp[0];
    if (lang < 0 || lang >= LL) {
        float f = __int_as_float(lang);
        int li = (int)f;
        lang = (li >= 0 && li < LL) ? li : 0;
    }
    int i = blockIdx.x * blockDim.x + threadIdx.x;
    if (i < EDIM*EDIM) {
        size_t off = (size_t)lang * EDIM * EDIM + i;
        g_W3[i]                     = __float2bfloat16_rn(Wq[i]);
        g_W3[(size_t)EDIM*EDIM + i] = __float2bfloat16_rn(Wk[i]);
        bf16 h, l;
        split1(Wvs[i] * Wvp[off], h, l);
        g_W3[(size_t)2*EDIM*EDIM + i] = h;
        g_Wvl[i] = l;
        split1(Wos[i] * Wop[off], g_Woh[i], g_Wol[i]);
    }
    if (i < EDIM) {
        g_b3[i]          = bq[i];
        g_b3[EDIM + i]   = bk[i];
        g_b3[2*EDIM + i] = bvs[i] + bvp[lang*EDIM + i];
        g_bo[i]          = bos[i] + bop[lang*EDIM + i];
    }
}

// ---------------- masked column sums of INPUT v (2-phase) ------------------
__global__ __launch_bounds__(512) void vsum1_kernel(
    const float* __restrict__ v, const int* __restrict__ mask)
{
    const int sc = blockIdx.x, b = blockIdx.y, e = threadIdx.x;
    float acc = 0.f;
    const int s0 = b*SS + sc*128;
#pragma unroll 4
    for (int s = 0; s < 128; s++)
        if (mask[s0 + s] != 0)
            acc += v[(size_t)(s0 + s)*EDIM + e];
    g_vsPart[(b*8 + sc)*EDIM + e] = acc;
    if (e == 0) {
        int c = 0;
        for (int s = 0; s < 128; s++) c += (mask[s0 + s] != 0);
        g_MsPart[b*8 + sc] = (float)c;
    }
}

__global__ __launch_bounds__(512) void vsum2_kernel()
{
    const int b = blockIdx.x, e = threadIdx.x;
    float acc = 0.f;
#pragma unroll
    for (int sc = 0; sc < 8; sc++) acc += g_vsPart[(b*8 + sc)*EDIM + e];
    g_vsum[b*EDIM + e] = acc;
    if (e == 0) {
        float c = 0.f;
#pragma unroll
        for (int sc = 0; sc < 8; sc++) c += g_MsPart[b*8 + sc];
        g_Msum[b] = c;
    }
}

// ---------------- Mv[b][n] = vsum[b] . Wv[n] + cnt*bv[n] (warp per out) ----
__global__ __launch_bounds__(256) void mv_gemm_kernel()
{
    const int w = blockIdx.x*8 + (threadIdx.x >> 5);   // 8192 warps
    const int lane = threadIdx.x & 31;
    const int b = w >> 9, n = w & 511;
    const bf16* Wvh = g_W3 + (size_t)2*EDIM*EDIM;
    float acc = 0.f;
#pragma unroll
    for (int t = 0; t < 16; t++) {
        int e = t*32 + lane;
        float wv = __bfloat162float(Wvh[(size_t)n*EDIM + e])
                 + __bfloat162float(g_Wvl[(size_t)n*EDIM + e]);
        acc = fmaf(g_vsum[b*EDIM + e], wv, acc);
    }
#pragma unroll
    for (int o = 16; o; o >>= 1) acc += __shfl_xor_sync(0xffffffffu, acc, o);
    if (lane == 0)
        g_Mv[b*EDIM + n] = acc + g_Msum[b]*g_b3[2*EDIM + n];
}

// ---------------- MW[b][n][h] = sum_{e in head h} Mv[b][e]*Wo[n][e] --------
__global__ __launch_bounds__(256) void mw_kernel()
{
    const int w = blockIdx.x*8 + (threadIdx.x >> 5);   // 8192 warps
    const int lane = threadIdx.x & 31;
    const int b = w >> 9, n = w & 511;
    float ph[8];
#pragma unroll
    for (int h = 0; h < 8; h++) ph[h] = 0.f;
#pragma unroll
    for (int t = 0; t < 16; t++) {
        int e = t*32 + lane;
        float wo = __bfloat162float(g_Woh[(size_t)n*EDIM + e])
                 + __bfloat162float(g_Wol[(size_t)n*EDIM + e]);
        ph[t >> 1] = fmaf(g_Mv[b*EDIM + e], wo, ph[t >> 1]);
    }
#pragma unroll
    for (int h = 0; h < 8; h++)
#pragma unroll
        for (int o = 16; o; o >>= 1)
            ph[h] += __shfl_xor_sync(0xffffffffu, ph[h], o);
    if (lane == 0) {
        float* dst = g_MW + ((size_t)b*EDIM + n)*8;
#pragma unroll
        for (int h = 0; h < 8; h++) dst[h] = ph[h];
    }
}

// =================== batched Q/K/V projection GEMM =========================
// One body; blockIdx.z selects operands by pointer arithmetic.
// z==0: Q (scale 1/64). z==1: K (mask rows). z==2: V.
#define GS_ROW   40
#define GS_ARRB  10240

__global__ __launch_bounds__(256, 2) void gemm_qkv(const int* __restrict__ maskp)
{
    extern __shared__ __align__(128) bf16 smem[];
    constexpr uint32_t STAGEB = 2 * GS_ARRB;

    const int tid  = threadIdx.x;
    const int lane = tid & 31;
    const int wid  = tid >> 5;
    const int wm   = wid >> 1;
    const int wn   = wid & 1;
    const int m0   = blockIdx.y * 128;
    const int n0   = blockIdx.x * 128;
    const int z    = blockIdx.z;

    const bf16* __restrict__ Ahi   = g_in3 + (size_t)z*MTOT*EDIM;
    const bf16* __restrict__ Bhi   = g_W3  + (size_t)z*EDIM*EDIM;
    bf16* __restrict__ outHi       = g_P3  + (size_t)z*MTOT*EDIM;
    const float* __restrict__ bias = g_b3 + z*EDIM;
    const float scale = (z == 0) ? (1.0f/64.0f) : 1.0f;

    const uint32_t sb = smem_u32(smem);

    auto cp_stage = [&](int ks, int buf) {
        uint32_t sbase = sb + (uint32_t)buf * STAGEB;
#pragma unroll
        for (int c8 = 0; c8 < 4; c8++) {
            int j = c8*256 + tid;
            int arr = j >> 9, jj = j & 511;
            int row = jj >> 2, cc = jj & 3;
            const bf16* src = (arr == 0)
                ? Ahi + (size_t)(m0+row)*EDIM + ks*32 + cc*8
                : Bhi + (size_t)(n0+row)*EDIM + ks*32 + cc*8;
            uint32_t dst = sbase + (uint32_t)arr*GS_ARRB + (uint32_t)(row*GS_ROW + cc*8)*2;
            cp16(dst, src);
        }
        cp_commit();
    };

    float d[2][8][4];
#pragma unroll
    for (int mt = 0; mt < 2; mt++)
#pragma unroll
        for (int nt = 0; nt < 8; nt++)
#pragma unroll
            for (int u = 0; u < 4; u++) d[mt][nt][u] = 0.f;

    cp_stage(0, 0);
    cp_stage(1, 1);

    for (int ks = 0; ks < 16; ks++) {
        if (ks < 15) cp_wait1(); else cp_wait0();
        __syncthreads();
        if (ks + 2 < 16) cp_stage(ks + 2, (ks + 2) % 3);

        const uint32_t base = sb + (uint32_t)(ks % 3) * STAGEB;
        const uint32_t aHi = base;
        const uint32_t bHi = base + GS_ARRB;

#pragma unroll
        for (int kk = 0; kk < 2; kk++) {
            const int kc = kk * 16;
            uint32_t ah[2][4];
            {
                int r = wm*32 + (lane & 7) + ((lane >> 3) & 1)*8;
                int k = kc + ((lane >> 4) & 1)*8;
                uint32_t off = (uint32_t)(r*GS_ROW + k)*2;
#pragma unroll
                for (int mt = 0; mt < 2; mt++)
                    ldsm_x4(aHi + off + (uint32_t)(mt*16*GS_ROW)*2, ah[mt]);
            }
            uint32_t bh[8][2];
            {
                int n = wn*64 + (lane & 7) + ((lane >> 4) & 1)*8;
                int k = kc + ((lane >> 3) & 1)*8;
                uint32_t off = (uint32_t)(n*GS_ROW + k)*2;
#pragma unroll
                for (int q = 0; q < 4; q++) {
                    uint32_t r4[4];
                    ldsm_x4(bHi + off + (uint32_t)(q*16*GS_ROW)*2, r4);
                    bh[2*q][0] = r4[0]; bh[2*q][1] = r4[1];
                    bh[2*q+1][0] = r4[2]; bh[2*q+1][1] = r4[3];
                }
            }
#pragma unroll
            for (int mt = 0; mt < 2; mt++)
#pragma unroll
                for (int nt = 0; nt < 8; nt++)
                    mma_bf16(d[mt][nt], ah[mt], bh[nt]);
        }
    }

    // epilogue
#pragma unroll
    for (int mt = 0; mt < 2; mt++) {
        int row0 = m0 + wm*32 + mt*16 + (lane >> 2);
        float mr0 = 1.f, mr1 = 1.f;
        if (z == 1) {
            mr0 = (maskp[row0] != 0) ? 1.f : 0.f;
            mr1 = (maskp[row0 + 8] != 0) ? 1.f : 0.f;
        }
#pragma unroll
        for (int nt = 0; nt < 8; nt++) {
            int col = n0 + wn*64 + nt*8 + (lane & 3)*2;
            float b0 = bias[col], b1 = bias[col + 1];
            float v0 = (d[mt][nt][0] + b0) * scale * mr0;
            float v1 = (d[mt][nt][1] + b1) * scale * mr0;
            float v2 = (d[mt][nt][2] + b0) * scale * mr1;
            float v3 = (d[mt][nt][3] + b1) * scale * mr1;
            size_t o0 = (size_t)row0*EDIM + col;
            size_t o1 = (size_t)(row0 + 8)*EDIM + col;
            *(uint32_t*)(outHi + o0) = pack_bf16x2(v0, v1);
            *(uint32_t*)(outHi + o1) = pack_bf16x2(v2, v3);
        }
    }
}

// =================== output projection (residual) + Mv epilogue ============
__global__ __launch_bounds__(256, 2) void gemm_out(
    float* __restrict__ outF)
{
    extern __shared__ __align__(128) bf16 smem[];
    constexpr uint32_t STAGEB = 2 * GS_ARRB;

    const int tid  = threadIdx.x;
    const int lane = tid & 31;
    const int wid  = tid >> 5;
    const int wm   = wid >> 1;
    const int wn   = wid & 1;
    const int m0   = blockIdx.y * 128;
    const int n0   = blockIdx.x * 128;

    const uint32_t sb = smem_u32(smem);

    auto cp_stage = [&](int ks, int buf) {
        uint32_t sbase = sb + (uint32_t)buf * STAGEB;
#pragma unroll
        for (int c8 = 0; c8 < 4; c8++) {
            int j = c8*256 + tid;
            int arr = j >> 9, jj = j & 511;
            int row = jj >> 2, cc = jj & 3;
            const bf16* src = (arr == 0)
                ? g_Ch  + (size_t)(m0+row)*EDIM + ks*32 + cc*8
                : g_Woh + (size_t)(n0+row)*EDIM + ks*32 + cc*8;
            uint32_t dst = sbase + (uint32_t)arr*GS_ARRB + (uint32_t)(row*GS_ROW + cc*8)*2;
            cp16(dst, src);
        }
        cp_commit();
    };

    float d[2][8][4];
#pragma unroll
    for (int mt = 0; mt < 2; mt++)
#pragma unroll
        for (int nt = 0; nt < 8; nt++)
#pragma unroll
            for (int u = 0; u < 4; u++) d[mt][nt][u] = 0.f;

    cp_stage(0, 0);
    cp_stage(1, 1);

    for (int ks = 0; ks < 16; ks++) {
        if (ks < 15) cp_wait1(); else cp_wait0();
        __syncthreads();
        if (ks + 2 < 16) cp_stage(ks + 2, (ks + 2) % 3);

        const uint32_t base = sb + (uint32_t)(ks % 3) * STAGEB;
        const uint32_t aHi = base;
        const uint32_t bHi = base + GS_ARRB;

#pragma unroll
        for (int kk = 0; kk < 2; kk++) {
            const int kc = kk * 16;
            uint32_t ah[2][4];
            {
                int r = wm*32 + (lane & 7) + ((lane >> 3) & 1)*8;
                int k = kc + ((lane >> 4) & 1)*8;
                uint32_t off = (uint32_t)(r*GS_ROW + k)*2;
#pragma unroll
                for (int mt = 0; mt < 2; mt++)
                    ldsm_x4(aHi + off + (uint32_t)(mt*16*GS_ROW)*2, ah[mt]);
            }
            uint32_t bh[8][2];
            {
                int n = wn*64 + (lane & 7) + ((lane >> 4) & 1)*8;
                int k = kc + ((lane >> 3) & 1)*8;
                uint32_t off = (uint32_t)(n*GS_ROW + k)*2;
#pragma unroll
                for (int q = 0; q < 4; q++) {
                    uint32_t r4[4];
                    ldsm_x4(bHi + off + (uint32_t)(q*16*GS_ROW)*2, r4);
                    bh[2*q][0] = r4[0]; bh[2*q][1] = r4[1];
                    bh[2*q+1][0] = r4[2]; bh[2*q+1][1] = r4[3];
                }
            }
#pragma unroll
            for (int mt = 0; mt < 2; mt++)
#pragma unroll
                for (int nt = 0; nt < 8; nt++)
                    mma_bf16(d[mt][nt], ah[mt], bh[nt]);
        }
    }

    // epilogue: + sum_h invl*MW + bias
#pragma unroll
    for (int mt = 0; mt < 2; mt++) {
        int row0 = m0 + wm*32 + mt*16 + (lane >> 2);
        float iv0[8], iv1[8];
        {
            const float* p0 = g_invl + (size_t)row0*8;
            const float* p1 = p0 + 64;
            float4 a0 = *(const float4*)p0, b0v = *(const float4*)(p0+4);
            float4 a1 = *(const float4*)p1, b1v = *(const float4*)(p1+4);
            iv0[0]=a0.x; iv0[1]=a0.y; iv0[2]=a0.z; iv0[3]=a0.w;
            iv0[4]=b0v.x; iv0[5]=b0v.y; iv0[6]=b0v.z; iv0[7]=b0v.w;
            iv1[0]=a1.x; iv1[1]=a1.y; iv1[2]=a1.z; iv1[3]=a1.w;
            iv1[4]=b1v.x; iv1[5]=b1v.y; iv1[6]=b1v.z; iv1[7]=b1v.w;
        }
#pragma unroll
        for (int nt = 0; nt < 8; nt++) {
            int col = n0 + wn*64 + nt*8 + (lane & 3)*2;
            float b0 = g_bo[col], b1 = g_bo[col + 1];
            size_t o0 = (size_t)row0*EDIM + col;
            size_t o1 = (size_t)(row0 + 8)*EDIM + col;
            const int bb = row0 >> 10;
            const float* mw0 = g_MW + ((size_t)bb*EDIM + col)*8;
            const float* mw1 = mw0 + 8;
            float dotA0 = 0.f, dotA1 = 0.f, dotB0 = 0.f, dotB1 = 0.f;
#pragma unroll
            for (int h = 0; h < 8; h++) {
                float m0v = mw0[h], m1v = mw1[h];
                dotA0 = fmaf(iv0[h], m0v, dotA0);
                dotA1 = fmaf(iv0[h], m1v, dotA1);
                dotB0 = fmaf(iv1[h], m0v, dotB0);
                dotB1 = fmaf(iv1[h], m1v, dotB1);
            }
            *(float2*)(outF + o0) = make_float2(d[mt][nt][0] + dotA0 + b0,
                                                d[mt][nt][1] + dotA1 + b1);
            *(float2*)(outF + o1) = make_float2(d[mt][nt][2] + dotB0 + b0,
                                                d[mt][nt][3] + dotB1 + b1);
        }
    }
}

// =================== attention: residual-only output ========================
#define AT_ROW   72
#define AT_QOFF  0
#define AT_KV(buf)   (18432 + (buf)*36864)
#define AT_VOFF(buf) (AT_KV(buf) + 18432)
#define ATTN_SMEM 92160

__global__ __launch_bounds__(256, 2) void attn_mma()
{
    extern __shared__ __align__(128) bf16 sm[];

    const int tid  = threadIdx.x;
    const int lane = tid & 31;
    const int wid  = tid >> 5;
    const int b    = blockIdx.z, h = blockIdx.y;
    const int q0   = blockIdx.x * 128;

    const bf16* __restrict__ Qh = g_P3;
    const bf16* __restrict__ Kh = g_P3 + (size_t)MTOT*EDIM;
    const bf16* __restrict__ Vh = g_P3 + (size_t)2*MTOT*EDIM;

    const uint32_t sb = smem_u32(sm);

    auto cp_kv = [&](int kb, int buf) {
#pragma unroll
        for (int c8 = 0; c8 < 8; c8++) {
            int j = c8*256 + tid;
            int arr = j >> 10, jj = j & 1023;
            int row = jj >> 3, cc = jj & 7;
            const bf16* src = (arr ? Vh : Kh)
                + (size_t)(b*SS + kb*128 + row)*EDIM + h*DD + cc*8;
            uint32_t dst = sb + (arr ? AT_VOFF(buf) : AT_KV(buf))
                + (uint32_t)(row*AT_ROW + cc*8)*2;
            cp16(dst, src);
        }
        cp_commit();
    };

#pragma unroll
    for (int c4 = 0; c4 < 4; c4++) {
        int j = c4*256 + tid;
        int row = j >> 3, cc = j & 7;
        uint4 v = *(const uint4*)(Qh + (size_t)(b*SS + q0 + row)*EDIM + h*DD + cc*8);
        uint32_t dst = sb + AT_QOFF + (uint32_t)(row*AT_ROW + cc*8)*2;
        asm volatile("st.shared.v4.b32 [%0], {%1,%2,%3,%4};"
                     :: "r"(dst), "r"(v.x), "r"(v.y), "r"(v.z), "r"(v.w));
    }
    cp_kv(0, 0);
    __syncthreads();

    uint32_t qf[4][4];
    {
        int r = wid*16 + (lane & 7) + ((lane >> 3) & 1)*8;
#pragma unroll
        for (int kc = 0; kc < 4; kc++) {
            int k = kc*16 + ((lane >> 4) & 1)*8;
            ldsm_x4(sb + AT_QOFF + (uint32_t)(r*AT_ROW + k)*2, qf[kc]);
        }
    }

    float l0 = 0.f, l1 = 0.f;
    float O[8][4];
#pragma unroll
    for (int nt = 0; nt < 8; nt++)
#pragma unroll
        for (int u = 0; u < 4; u++) O[nt][u] = 0.f;

    for (int kb = 0; kb < SS/128; kb++) {
        cp_wait0();
        __syncthreads();
        if (kb + 1 < SS/128) cp_kv(kb + 1, (kb + 1) & 1);
        const uint32_t Kbuf = sb + AT_KV(kb & 1);
        const uint32_t Vbuf = sb + AT_VOFF(kb & 1);

#pragma unroll
        for (int p = 0; p < 8; p++) {
            float S0[4] = {0.f, 0.f, 0.f, 0.f};
            float S1[4] = {0.f, 0.f, 0.f, 0.f};
#pragma unroll
            for (int c = 0; c < 4; c++) {
                int n = 16*p + (lane & 7) + ((lane >> 4) & 1)*8;
                int k = c*16 + ((lane >> 3) & 1)*8;
                uint32_t r4[4], b0[2], b1[2];
                ldsm_x4(Kbuf + (uint32_t)(n*AT_ROW + k)*2, r4);
                b0[0]=r4[0]; b0[1]=r4[1]; b1[0]=r4[2]; b1[1]=r4[3];
                mma_bf16(S0, qf[c], b0);
                mma_bf16(S1, qf[c], b1);
            }

            float u00 = expm1_poly(S0[0]), u01 = expm1_poly(S0[1]);
            float u02 = expm1_poly(S0[2]), u03 = expm1_poly(S0[3]);
            float u10 = expm1_poly(S1[0]), u11 = expm1_poly(S1[1]);
            float u12 = expm1_poly(S1[2]), u13 = expm1_poly(S1[3]);
            l0 += u00 + u01 + u10 + u11;
            l1 += u02 + u03 + u12 + u13;

            uint32_t ua[4];
            ua[0] = pack_bf16x2(u00, u01);
            ua[1] = pack_bf16x2(u02, u03);
            ua[2] = pack_bf16x2(u10, u11);
            ua[3] = pack_bf16x2(u12, u13);

#pragma unroll
            for (int np = 0; np < 4; np++) {
                int rs = p*16 + (lane & 7) + ((lane >> 3) & 1)*8;
                int cd = np*16 + ((lane >> 4) & 1)*8;
                uint32_t r4[4], b0[2], b1[2];
                ldsm_x4_t(Vbuf + (uint32_t)(rs*AT_ROW + cd)*2, r4);
                b0[0]=r4[0]; b0[1]=r4[1]; b1[0]=r4[2]; b1[1]=r4[3];
                mma_bf16(O[2*np],   ua, b0);
                mma_bf16(O[2*np+1], ua, b1);
            }
        }
    }

#pragma unroll
    for (int off = 1; off <= 2; off <<= 1) {
        l0 += __shfl_xor_sync(0xffffffffu, l0, off);
        l1 += __shfl_xor_sync(0xffffffffu, l1, off);
    }
    float msum = g_Msum[b];
    float inv0 = 1.f / (msum + l0), inv1 = 1.f / (msum + l1);

    int r0 = q0 + wid*16 + (lane >> 2);
    int r1 = r0 + 8;
    if ((lane & 3) == 0) {
        g_invl[((size_t)b*SS + r0)*8 + h] = inv0;
        g_invl[((size_t)b*SS + r1)*8 + h] = inv1;
    }
#pragma unroll
    for (int nt = 0; nt < 8; nt++) {
        int dcol = nt*8 + (lane & 3)*2;
        size_t o0 = (size_t)(b*SS + r0)*EDIM + h*DD + dcol;
        size_t o1 = (size_t)(b*SS + r1)*EDIM + h*DD + dcol;
        *(uint32_t*)(g_Ch + o0) = pack_bf16x2(O[nt][0]*inv0, O[nt][1]*inv0);
        *(uint32_t*)(g_Ch + o1) = pack_bf16x2(O[nt][2]*inv1, O[nt][3]*inv1);
    }
}

// ---------------- launch ----------------------------------------------------
extern "C" void kernel_launch(void* const* d_in, const int* in_sizes, int n_in,
                              void* d_out, int out_size)
{
    const float* q        = (const float*)d_in[0];
    const float* k        = (const float*)d_in[1];
    const float* v        = (const float*)d_in[2];
    const float* Wq       = (const float*)d_in[3];
    const float* bq       = (const float*)d_in[4];
    const float* Wk       = (const float*)d_in[5];
    const float* bk       = (const float*)d_in[6];
    const float* Wv_share = (const float*)d_in[7];
    const float* Wv_spec  = (const float*)d_in[8];
    const float* bv_share = (const float*)d_in[9];
    const float* bv_spec  = (const float*)d_in[10];
    const float* Wo_share = (const float*)d_in[11];
    const float* Wo_spec  = (const float*)d_in[12];
    const float* bo_share = (const float*)d_in[13];
    const float* bo_spec  = (const float*)d_in[14];
    const int*   mask     = (const int*)d_in[15];
    const int*   langp    = (const int*)d_in[16];
    float*       out      = (float*)d_out;

    const int DS1 = 3*2*GS_ARRB;   // 61440
    cudaFuncSetAttribute(attn_mma,
                         cudaFuncAttributeMaxDynamicSharedMemorySize, ATTN_SMEM);
    cudaFuncSetAttribute(gemm_qkv,
                         cudaFuncAttributeMaxDynamicSharedMemorySize, DS1);
    cudaFuncSetAttribute(gemm_out,
                         cudaFuncAttributeMaxDynamicSharedMemorySize, DS1);

    // 1. input splits + weight fuse/split
    split3_kernel<<<24576, 256>>>(q, k, v);
    fuse_weights_kernel<<<1024, 256>>>(Wq, Wk, bq, bk, Wv_share, Wv_spec,
                                       bv_share, bv_spec, Wo_share, Wo_spec,
                                       bo_share, bo_spec, langp);

    // 2. masked column sums of input v + counts
    dim3 gv1(8, BB);
    vsum1_kernel<<<gv1, 512>>>(v, mask);
    vsum2_kernel<<<BB, 512>>>();

    // 3. batched Q/K/V projections (one launch)
    dim3 gqkv(EDIM/128, MTOT/128, 3);
    gemm_qkv<<<gqkv, 256, DS1>>>(mask);

    // 4. Mv (fp32 analytic) and MW precompute
    mv_gemm_kernel<<<1024, 256>>>();
    mw_kernel<<<1024, 256>>>();

    // 5. attention -> residual C (bf16) + invl
    dim3 ga(SS/128, HH, BB);
    attn_mma<<<ga, 256, ATTN_SMEM>>>();

    // 6. output projection (residual) + Mv-path epilogue -> d_out (fp32)
    dim3 go(EDIM/128, MTOT/128);
    gemm_out<<<go, 256, DS1>>>(out);
}